// round 2
// baseline (speedup 1.0000x reference)
#include <cuda_runtime.h>
#include <cuda_bf16.h>
#include <cstdint>

#define HID 2048
#define STATE 128
#define HEADS 64
#define HEADDIM 64
#define INTER 4096
#define CONV_DIM 4352
#define PROJ_DIM 8512
#define NTOK 4096
#define SEQ 2048
#define EPSV 1e-5f

// ---------------- scratch (device globals: no cudaMalloc allowed) ----------------
__device__ float g_xn[(size_t)NTOK * HID];         // rmsnormed input (33.5MB)
__device__ float g_proj[(size_t)NTOK * PROJ_DIM];  // in_proj output (139MB)
__device__ float g_xs[(size_t)NTOK * INTER];       // conv+silu x (67MB)
__device__ float g_Bm[(size_t)NTOK * STATE];
__device__ float g_Cm[(size_t)NTOK * STATE];
__device__ float g_dt[(size_t)NTOK * HEADS];
__device__ float g_dA[(size_t)NTOK * HEADS];
__device__ float g_y[(size_t)NTOK * INTER];        // scan output (67MB)
__device__ float g_yn[(size_t)NTOK * INTER];       // gated-norm output (67MB)

// ---------------- helpers ----------------
__device__ __forceinline__ uint32_t f2tf(float f) {
    uint32_t r;
    asm("cvt.rna.tf32.f32 %0, %1;" : "=r"(r) : "f"(f));
    return r;
}

__device__ __forceinline__ float block_reduce_sum(float v) {
    __shared__ float sh[32];
    int lane = threadIdx.x & 31, w = threadIdx.x >> 5;
    #pragma unroll
    for (int o = 16; o; o >>= 1) v += __shfl_xor_sync(0xffffffffu, v, o);
    if (lane == 0) sh[w] = v;
    __syncthreads();
    int nw = blockDim.x >> 5;
    float t = (threadIdx.x < (unsigned)nw) ? sh[threadIdx.x] : 0.f;
    if (w == 0) {
        #pragma unroll
        for (int o = 16; o; o >>= 1) t += __shfl_xor_sync(0xffffffffu, t, o);
        if (lane == 0) sh[0] = t;
    }
    __syncthreads();
    return sh[0];
}

// ---------------- stage 1: input rmsnorm ----------------
__global__ __launch_bounds__(256) void rmsnorm_in_kernel(
    const float* __restrict__ x, const float* __restrict__ w) {
    int row = blockIdx.x;
    const float* xr = x + (size_t)row * HID;
    float vals[8];
    float ss = 0.f;
    #pragma unroll
    for (int i = 0; i < 8; i++) {
        int idx = threadIdx.x + i * 256;
        float v = xr[idx];
        vals[i] = v;
        ss += v * v;
    }
    float tot = block_reduce_sum(ss);
    float scale = rsqrtf(tot * (1.f / HID) + EPSV);
    float* orow = g_xn + (size_t)row * HID;
    #pragma unroll
    for (int i = 0; i < 8; i++) {
        int idx = threadIdx.x + i * 256;
        orow[idx] = vals[i] * scale * w[idx];
    }
}

// ---------------- TF32 NT GEMM: C[M,N] = A[M,K] * B[N,K]^T (+ residual) ----------------
#define BM 128
#define BN 128
#define BKK 16

__global__ __launch_bounds__(256) void gemm_tf32_nt(
    const float* __restrict__ A, const float* __restrict__ Bw,
    float* __restrict__ C, const float* __restrict__ Res,
    int M, int N, int K) {
    __shared__ uint32_t As[2][BM][BKK + 4];
    __shared__ uint32_t Bs[2][BN][BKK + 4];

    int tid = threadIdx.x;
    int mBase = blockIdx.y * BM, nBase = blockIdx.x * BN;
    int wid = tid >> 5, lane = tid & 31;
    int wm = wid >> 2, wn = wid & 3;   // 2 x 4 warp grid
    int g = lane >> 2, tg = lane & 3;

    float acc[4][4][4];
    #pragma unroll
    for (int a = 0; a < 4; a++)
        #pragma unroll
        for (int b = 0; b < 4; b++)
            #pragma unroll
            for (int c = 0; c < 4; c++) acc[a][b][c] = 0.f;

    int r0 = tid >> 2;        // 0..63
    int r1 = r0 + 64;         // 64..127
    int c4 = (tid & 3) << 2;  // 0,4,8,12
    int nk = K / BKK;

    float4 ra0, ra1, rb0, rb1;
    float4 z4 = make_float4(0.f, 0.f, 0.f, 0.f);

    // prologue loads for tile 0
    {
        int arow0 = mBase + r0, arow1 = mBase + r1;
        int brow0 = nBase + r0, brow1 = nBase + r1;
        ra0 = (arow0 < M) ? *(const float4*)(A + (size_t)arow0 * K + c4) : z4;
        ra1 = (arow1 < M) ? *(const float4*)(A + (size_t)arow1 * K + c4) : z4;
        rb0 = (brow0 < N) ? *(const float4*)(Bw + (size_t)brow0 * K + c4) : z4;
        rb1 = (brow1 < N) ? *(const float4*)(Bw + (size_t)brow1 * K + c4) : z4;
    }
    // store tile 0
    {
        uint32_t* p;
        p = &As[0][r0][c4]; p[0]=f2tf(ra0.x); p[1]=f2tf(ra0.y); p[2]=f2tf(ra0.z); p[3]=f2tf(ra0.w);
        p = &As[0][r1][c4]; p[0]=f2tf(ra1.x); p[1]=f2tf(ra1.y); p[2]=f2tf(ra1.z); p[3]=f2tf(ra1.w);
        p = &Bs[0][r0][c4]; p[0]=f2tf(rb0.x); p[1]=f2tf(rb0.y); p[2]=f2tf(rb0.z); p[3]=f2tf(rb0.w);
        p = &Bs[0][r1][c4]; p[0]=f2tf(rb1.x); p[1]=f2tf(rb1.y); p[2]=f2tf(rb1.z); p[3]=f2tf(rb1.w);
    }
    __syncthreads();

    for (int kt = 0; kt < nk; ++kt) {
        int cur = kt & 1;
        if (kt + 1 < nk) {
            int k0 = (kt + 1) * BKK + c4;
            int arow0 = mBase + r0, arow1 = mBase + r1;
            int brow0 = nBase + r0, brow1 = nBase + r1;
            ra0 = (arow0 < M) ? *(const float4*)(A + (size_t)arow0 * K + k0) : z4;
            ra1 = (arow1 < M) ? *(const float4*)(A + (size_t)arow1 * K + k0) : z4;
            rb0 = (brow0 < N) ? *(const float4*)(Bw + (size_t)brow0 * K + k0) : z4;
            rb1 = (brow1 < N) ? *(const float4*)(Bw + (size_t)brow1 * K + k0) : z4;
        }
        #pragma unroll
        for (int kk = 0; kk < 2; ++kk) {
            uint32_t af[4][4], bf[4][2];
            int col = kk * 8 + tg;
            #pragma unroll
            for (int mt = 0; mt < 4; ++mt) {
                int row = wm * 64 + mt * 16 + g;
                af[mt][0] = As[cur][row][col];
                af[mt][1] = As[cur][row + 8][col];
                af[mt][2] = As[cur][row][col + 4];
                af[mt][3] = As[cur][row + 8][col + 4];
            }
            #pragma unroll
            for (int nt = 0; nt < 4; ++nt) {
                int nrow = wn * 32 + nt * 8 + g;
                bf[nt][0] = Bs[cur][nrow][col];
                bf[nt][1] = Bs[cur][nrow][col + 4];
            }
            #pragma unroll
            for (int mt = 0; mt < 4; ++mt)
                #pragma unroll
                for (int nt = 0; nt < 4; ++nt) {
                    asm volatile(
                        "mma.sync.aligned.m16n8k8.row.col.f32.tf32.tf32.f32 "
                        "{%0,%1,%2,%3},{%4,%5,%6,%7},{%8,%9},{%0,%1,%2,%3};\n"
                        : "+f"(acc[mt][nt][0]), "+f"(acc[mt][nt][1]),
                          "+f"(acc[mt][nt][2]), "+f"(acc[mt][nt][3])
                        : "r"(af[mt][0]), "r"(af[mt][1]), "r"(af[mt][2]), "r"(af[mt][3]),
                          "r"(bf[nt][0]), "r"(bf[nt][1]));
                }
        }
        if (kt + 1 < nk) {
            int nxt = cur ^ 1;
            uint32_t* p;
            p = &As[nxt][r0][c4]; p[0]=f2tf(ra0.x); p[1]=f2tf(ra0.y); p[2]=f2tf(ra0.z); p[3]=f2tf(ra0.w);
            p = &As[nxt][r1][c4]; p[0]=f2tf(ra1.x); p[1]=f2tf(ra1.y); p[2]=f2tf(ra1.z); p[3]=f2tf(ra1.w);
            p = &Bs[nxt][r0][c4]; p[0]=f2tf(rb0.x); p[1]=f2tf(rb0.y); p[2]=f2tf(rb0.z); p[3]=f2tf(rb0.w);
            p = &Bs[nxt][r1][c4]; p[0]=f2tf(rb1.x); p[1]=f2tf(rb1.y); p[2]=f2tf(rb1.z); p[3]=f2tf(rb1.w);
            __syncthreads();
        }
    }

    // epilogue
    #pragma unroll
    for (int mt = 0; mt < 4; ++mt) {
        int row0 = mBase + wm * 64 + mt * 16 + g;
        #pragma unroll
        for (int nt = 0; nt < 4; ++nt) {
            int col = nBase + wn * 32 + nt * 8 + tg * 2;
            if (col + 1 < N || col < N) {
                // element (row0, col), (row0, col+1), (row0+8, col), (row0+8, col+1)
                if (row0 < M && col < N) {
                    float v0 = acc[mt][nt][0];
                    float v1 = acc[mt][nt][1];
                    if (Res) {
                        v0 += Res[(size_t)row0 * N + col];
                        if (col + 1 < N) v1 += Res[(size_t)row0 * N + col + 1];
                    }
                    C[(size_t)row0 * N + col] = v0;
                    if (col + 1 < N) C[(size_t)row0 * N + col + 1] = v1;
                }
                int row1 = row0 + 8;
                if (row1 < M && col < N) {
                    float v2 = acc[mt][nt][2];
                    float v3 = acc[mt][nt][3];
                    if (Res) {
                        v2 += Res[(size_t)row1 * N + col];
                        if (col + 1 < N) v3 += Res[(size_t)row1 * N + col + 1];
                    }
                    C[(size_t)row1 * N + col] = v2;
                    if (col + 1 < N) C[(size_t)row1 * N + col + 1] = v3;
                }
            }
        }
    }
}

// ---------------- stage 3: causal depthwise conv (K=4) + SiLU + split ----------------
__global__ __launch_bounds__(128) void conv_kernel(
    const float* __restrict__ conv_w, const float* __restrict__ conv_b) {
    int c = blockIdx.x * 128 + threadIdx.x;  // 0..4351
    int t0 = blockIdx.y * 64;
    float w0 = conv_w[c * 4 + 0];
    float w1 = conv_w[c * 4 + 1];
    float w2 = conv_w[c * 4 + 2];
    float w3 = conv_w[c * 4 + 3];
    float bias = conv_b[c];
    const float* col = g_proj + INTER + c;
    float h0, h1, h2;
    if ((t0 & (SEQ - 1)) == 0) {
        h0 = h1 = h2 = 0.f;
    } else {
        h0 = col[(size_t)(t0 - 3) * PROJ_DIM];
        h1 = col[(size_t)(t0 - 2) * PROJ_DIM];
        h2 = col[(size_t)(t0 - 1) * PROJ_DIM];
    }
    for (int i = 0; i < 64; i++) {
        int t = t0 + i;
        float xc = col[(size_t)t * PROJ_DIM];
        float a = bias + w0 * h0 + w1 * h1 + w2 * h2 + w3 * xc;
        float v = a / (1.f + expf(-a));  // silu
        if (c < INTER)
            g_xs[(size_t)t * INTER + c] = v;
        else if (c < INTER + STATE)
            g_Bm[(size_t)t * STATE + (c - INTER)] = v;
        else
            g_Cm[(size_t)t * STATE + (c - INTER - STATE)] = v;
        h0 = h1; h1 = h2; h2 = xc;
    }
}

// ---------------- stage 4: dt = softplus(raw + bias), dA = exp(dt * -exp(A_log)) ----------------
__global__ __launch_bounds__(256) void dt_kernel(
    const float* __restrict__ dt_bias, const float* __restrict__ A_log) {
    int i = blockIdx.x * 256 + threadIdx.x;
    if (i >= NTOK * HEADS) return;
    int h = i & (HEADS - 1);
    int tok = i >> 6;
    float raw = g_proj[(size_t)tok * PROJ_DIM + INTER + CONV_DIM + h];
    float s = raw + dt_bias[h];
    float dtv = (s > 20.f) ? s : log1pf(expf(s));
    float A = -expf(A_log[h]);
    g_dt[i] = dtv;
    g_dA[i] = expf(dtv * A);
}

// ---------------- stage 5: selective scan ----------------
// block = (head, batch). 256 threads. lane: pi=lane&7 (p within warp), nc=lane>>3
// thread owns p = warp*8+pi and n in [nc*32, nc*32+32). y reduced with 2 shfl.
__global__ __launch_bounds__(256) void scan_kernel(const float* __restrict__ Dv) {
    int h = blockIdx.x, b = blockIdx.y;
    int lane = threadIdx.x & 31, w = threadIdx.x >> 5;
    int pi = lane & 7, nc = lane >> 3;
    int p = w * 8 + pi;
    float st[32];
    #pragma unroll
    for (int i = 0; i < 32; i++) st[i] = 0.f;
    float Dh = Dv[h];
    size_t tokBase = (size_t)b * SEQ;
    const float* xp = g_xs + tokBase * INTER + h * HEADDIM + p;
    const float4* Bp = (const float4*)(g_Bm + tokBase * STATE + nc * 32);
    const float4* Cp = (const float4*)(g_Cm + tokBase * STATE + nc * 32);
    const float* dAp = g_dA + tokBase * HEADS + h;
    const float* dtp = g_dt + tokBase * HEADS + h;
    float* yo = g_y + tokBase * INTER + h * HEADDIM + p;

    for (int t = 0; t < SEQ; t++) {
        float dAv = dAp[(size_t)t * HEADS];
        float dtv = dtp[(size_t)t * HEADS];
        float xv = xp[(size_t)t * INTER];
        float xdt = xv * dtv;
        const float4* B4 = Bp + (size_t)t * (STATE / 4);
        const float4* C4 = Cp + (size_t)t * (STATE / 4);
        float y0 = 0.f, y1 = 0.f, y2 = 0.f, y3 = 0.f;
        #pragma unroll
        for (int j = 0; j < 8; j++) {
            float4 bv = B4[j];
            float4 cv = C4[j];
            float s0 = st[4 * j + 0] * dAv + xdt * bv.x; st[4 * j + 0] = s0; y0 += s0 * cv.x;
            float s1 = st[4 * j + 1] * dAv + xdt * bv.y; st[4 * j + 1] = s1; y1 += s1 * cv.y;
            float s2 = st[4 * j + 2] * dAv + xdt * bv.z; st[4 * j + 2] = s2; y2 += s2 * cv.z;
            float s3 = st[4 * j + 3] * dAv + xdt * bv.w; st[4 * j + 3] = s3; y3 += s3 * cv.w;
        }
        float ys = (y0 + y1) + (y2 + y3);
        ys += __shfl_xor_sync(0xffffffffu, ys, 8);
        ys += __shfl_xor_sync(0xffffffffu, ys, 16);
        if (nc == 0) yo[(size_t)t * INTER] = ys + Dh * xv;
    }
}

// ---------------- stage 6: gated rmsnorm ----------------
__global__ __launch_bounds__(256) void gatenorm_kernel(const float* __restrict__ gnw) {
    int row = blockIdx.x;
    const float* yrow = g_y + (size_t)row * INTER;
    const float* grow = g_proj + (size_t)row * PROJ_DIM;  // gate = proj[:, :INTER]
    float vals[16];
    float ss = 0.f;
    #pragma unroll
    for (int i = 0; i < 16; i++) {
        int idx = threadIdx.x + i * 256;
        float gt = grow[idx];
        float v = yrow[idx] * (gt / (1.f + expf(-gt)));
        vals[i] = v;
        ss += v * v;
    }
    float tot = block_reduce_sum(ss);
    float scale = rsqrtf(tot * (1.f / INTER) + EPSV);
    float* orow = g_yn + (size_t)row * INTER;
    #pragma unroll
    for (int i = 0; i < 16; i++) {
        int idx = threadIdx.x + i * 256;
        orow[idx] = vals[i] * scale * gnw[idx];
    }
}

// ---------------- launch ----------------
extern "C" void kernel_launch(void* const* d_in, const int* in_sizes, int n_in,
                              void* d_out, int out_size) {
    const float* hidden  = (const float*)d_in[0];
    const float* norm_w  = (const float*)d_in[1];
    const float* in_proj = (const float*)d_in[2];
    const float* conv_w  = (const float*)d_in[3];
    const float* conv_b  = (const float*)d_in[4];
    const float* dt_bias = (const float*)d_in[5];
    const float* A_log   = (const float*)d_in[6];
    const float* Dvec    = (const float*)d_in[7];
    const float* gnw     = (const float*)d_in[8];
    const float* out_w   = (const float*)d_in[9];

    float *p_xn, *p_proj, *p_yn;
    cudaGetSymbolAddress((void**)&p_xn, g_xn);
    cudaGetSymbolAddress((void**)&p_proj, g_proj);
    cudaGetSymbolAddress((void**)&p_yn, g_yn);

    rmsnorm_in_kernel<<<NTOK, 256>>>(hidden, norm_w);

    gemm_tf32_nt<<<dim3((PROJ_DIM + BN - 1) / BN, NTOK / BM), 256>>>(
        p_xn, in_proj, p_proj, nullptr, NTOK, PROJ_DIM, HID);

    conv_kernel<<<dim3(CONV_DIM / 128, NTOK / 64), 128>>>(conv_w, conv_b);

    dt_kernel<<<(NTOK * HEADS) / 256, 256>>>(dt_bias, A_log);

    scan_kernel<<<dim3(HEADS, 2), 256>>>(Dvec);

    gatenorm_kernel<<<NTOK, 256>>>(gnw);

    gemm_tf32_nt<<<dim3(HID / BN, NTOK / BM), 256>>>(
        p_yn, out_w, (float*)d_out, hidden, NTOK, HID, INTER);
}

// round 4
// speedup vs baseline: 1.1275x; 1.1275x over previous
#include <cuda_runtime.h>
#include <cuda_bf16.h>
#include <cstdint>

#define HID 2048
#define STATE 128
#define HEADS 64
#define HEADDIM 64
#define INTER 4096
#define CONV_DIM 4352
#define PROJ_DIM 8512
#define NTOK 4096
#define SEQ 2048
#define EPSV 1e-5f

// ---------------- scratch (device globals: no cudaMalloc allowed) ----------------
__device__ float g_xn[(size_t)NTOK * HID];         // rmsnormed input, tf32-rounded
__device__ float g_proj[(size_t)NTOK * PROJ_DIM];  // in_proj output
__device__ float g_xs[(size_t)NTOK * INTER];       // conv+silu x
__device__ float g_Bm[(size_t)NTOK * STATE];
__device__ float g_Cm[(size_t)NTOK * STATE];
__device__ float g_dt[(size_t)NTOK * HEADS];
__device__ float g_dA[(size_t)NTOK * HEADS];
__device__ float g_y[(size_t)NTOK * INTER];        // scan output
__device__ float g_yn[(size_t)NTOK * INTER];       // gated-norm output, tf32-rounded
__device__ float g_wa[(size_t)PROJ_DIM * HID];     // in_proj weights, tf32-rounded
__device__ float g_wb[(size_t)HID * INTER];        // out_proj weights, tf32-rounded

// ---------------- helpers ----------------
__device__ __forceinline__ uint32_t f2tf(float f) {
    uint32_t r;
    asm("cvt.rna.tf32.f32 %0, %1;" : "=r"(r) : "f"(f));
    return r;
}

__device__ __forceinline__ uint32_t smem_u32(const void* p) {
    uint32_t a;
    asm("{ .reg .u64 t; cvta.to.shared.u64 t, %1; cvt.u32.u64 %0, t; }" : "=r"(a) : "l"(p));
    return a;
}

#define CP_ASYNC16(saddr, gptr) \
    asm volatile("cp.async.cg.shared.global [%0], [%1], 16;" :: "r"(saddr), "l"(gptr) : "memory")
#define CP_COMMIT() asm volatile("cp.async.commit_group;" ::: "memory")
#define CP_WAIT2()  asm volatile("cp.async.wait_group 2;" ::: "memory")

__device__ __forceinline__ float block_reduce_sum(float v) {
    __shared__ float sh[32];
    int lane = threadIdx.x & 31, w = threadIdx.x >> 5;
    #pragma unroll
    for (int o = 16; o; o >>= 1) v += __shfl_xor_sync(0xffffffffu, v, o);
    if (lane == 0) sh[w] = v;
    __syncthreads();
    int nw = blockDim.x >> 5;
    float t = (threadIdx.x < (unsigned)nw) ? sh[threadIdx.x] : 0.f;
    if (w == 0) {
        #pragma unroll
        for (int o = 16; o; o >>= 1) t += __shfl_xor_sync(0xffffffffu, t, o);
        if (lane == 0) sh[0] = t;
    }
    __syncthreads();
    return sh[0];
}

// ---------------- stage 0: convert weights to tf32 bits ----------------
__global__ __launch_bounds__(256) void tf32_cvt_kernel(
    const float* __restrict__ in, float* __restrict__ out, int n4) {
    int i = blockIdx.x * 256 + threadIdx.x;
    if (i >= n4) return;
    float4 v = ((const float4*)in)[i];
    uint4 u;
    u.x = f2tf(v.x); u.y = f2tf(v.y); u.z = f2tf(v.z); u.w = f2tf(v.w);
    ((uint4*)out)[i] = u;
}

// ---------------- stage 1: input rmsnorm (writes tf32-rounded) ----------------
__global__ __launch_bounds__(256) void rmsnorm_in_kernel(
    const float* __restrict__ x, const float* __restrict__ w) {
    int row = blockIdx.x;
    const float* xr = x + (size_t)row * HID;
    float vals[8];
    float ss = 0.f;
    #pragma unroll
    for (int i = 0; i < 8; i++) {
        int idx = threadIdx.x + i * 256;
        float v = xr[idx];
        vals[i] = v;
        ss += v * v;
    }
    float tot = block_reduce_sum(ss);
    float scale = rsqrtf(tot * (1.f / HID) + EPSV);
    float* orow = g_xn + (size_t)row * HID;
    #pragma unroll
    for (int i = 0; i < 8; i++) {
        int idx = threadIdx.x + i * 256;
        orow[idx] = __uint_as_float(f2tf(vals[i] * scale * w[idx]));
    }
}

// ---------------- TF32 NT GEMM, cp.async 3-stage: C[M,N] = A*B^T (+Res) ----------------
// Operands must already be tf32-rounded floats. 128x128x32 CTA tile, 256 thr.
#define BK 32
#define LDK 36
#define STAGE_FLOATS (128 * LDK)
#define GEMM_SMEM (3 * 2 * STAGE_FLOATS * 4)   // 110592 B

__global__ __launch_bounds__(256) void gemm_tf32_nt(
    const float* __restrict__ A, const float* __restrict__ Bw,
    float* __restrict__ C, const float* __restrict__ Res,
    int M, int N, int K) {
    extern __shared__ float smf[];
    float* As = smf;                       // [3][128][LDK]
    float* Bs = smf + 3 * STAGE_FLOATS;
    uint32_t sA = smem_u32(As), sB = smem_u32(Bs);

    int tid = threadIdx.x;
    int mBase = blockIdx.y * 128, nBase = blockIdx.x * 128;
    int nn = N - nBase; if (nn > 128) nn = 128;
    int wid = tid >> 5, lane = tid & 31;
    int wm = wid >> 2, wn = wid & 3;     // 2 x 4 warps, warptile 64x32
    int g = lane >> 2, tg = lane & 3;
    int nk = K / BK;

    float acc[4][4][4];
    #pragma unroll
    for (int a = 0; a < 4; a++)
        #pragma unroll
        for (int b = 0; b < 4; b++)
            #pragma unroll
            for (int c = 0; c < 4; c++) acc[a][b][c] = 0.f;

    // ---- async tile loader: tile kt -> stage s ----
    auto issue_tile = [&](int kt, int s) {
        size_t gk = (size_t)kt * BK;
        #pragma unroll
        for (int i = 0; i < 4; i++) {
            int idx = tid + i * 256;
            int row = idx >> 3, c4 = (idx & 7) * 4;
            uint32_t sa = sA + (uint32_t)(s * STAGE_FLOATS + row * LDK + c4) * 4u;
            CP_ASYNC16(sa, A + (size_t)(mBase + row) * K + gk + c4);
        }
        #pragma unroll
        for (int i = 0; i < 4; i++) {
            int idx = tid + i * 256;
            int row = idx >> 3, c4 = (idx & 7) * 4;
            if (nBase + row < N) {
                uint32_t sb2 = sB + (uint32_t)(s * STAGE_FLOATS + row * LDK + c4) * 4u;
                CP_ASYNC16(sb2, Bw + (size_t)(nBase + row) * K + gk + c4);
            }
        }
        CP_COMMIT();
    };

    issue_tile(0, 0);
    issue_tile(1, 1);

    int s_next = 2;
    for (int kt = 0; kt < nk; ++kt) {
        if (kt + 2 < nk) {
            issue_tile(kt + 2, s_next);
        } else {
            CP_COMMIT();   // empty group keeps wait_group accounting simple
        }
        s_next++; if (s_next == 3) s_next = 0;
        CP_WAIT2();
        __syncthreads();

        int cur = kt % 3;
        const float* a_st = As + cur * STAGE_FLOATS;
        const float* b_st = Bs + cur * STAGE_FLOATS;
        #pragma unroll
        for (int kk = 0; kk < 4; ++kk) {
            uint32_t af[4][4], bf[4][2];
            int col = kk * 8 + tg;
            #pragma unroll
            for (int mt = 0; mt < 4; ++mt) {
                int row = wm * 64 + mt * 16 + g;
                af[mt][0] = __float_as_uint(a_st[row * LDK + col]);
                af[mt][1] = __float_as_uint(a_st[(row + 8) * LDK + col]);
                af[mt][2] = __float_as_uint(a_st[row * LDK + col + 4]);
                af[mt][3] = __float_as_uint(a_st[(row + 8) * LDK + col + 4]);
            }
            #pragma unroll
            for (int nt = 0; nt < 4; ++nt) {
                int nrow = wn * 32 + nt * 8 + g;
                bf[nt][0] = __float_as_uint(b_st[nrow * LDK + col]);
                bf[nt][1] = __float_as_uint(b_st[nrow * LDK + col + 4]);
            }
            #pragma unroll
            for (int mt = 0; mt < 4; ++mt)
                #pragma unroll
                for (int nt = 0; nt < 4; ++nt) {
                    asm volatile(
                        "mma.sync.aligned.m16n8k8.row.col.f32.tf32.tf32.f32 "
                        "{%0,%1,%2,%3},{%4,%5,%6,%7},{%8,%9},{%0,%1,%2,%3};\n"
                        : "+f"(acc[mt][nt][0]), "+f"(acc[mt][nt][1]),
                          "+f"(acc[mt][nt][2]), "+f"(acc[mt][nt][3])
                        : "r"(af[mt][0]), "r"(af[mt][1]), "r"(af[mt][2]), "r"(af[mt][3]),
                          "r"(bf[nt][0]), "r"(bf[nt][1]));
                }
        }
        __syncthreads();
    }

    // epilogue (direct from regs; same mapping as the verified R1 kernel)
    #pragma unroll
    for (int mt = 0; mt < 4; ++mt) {
        int row0 = mBase + wm * 64 + mt * 16 + g;
        #pragma unroll
        for (int nt = 0; nt < 4; ++nt) {
            int col = nBase + wn * 32 + nt * 8 + tg * 2;
            if (col < N) {
                float v0 = acc[mt][nt][0];
                float v1 = acc[mt][nt][1];
                float v2 = acc[mt][nt][2];
                float v3 = acc[mt][nt][3];
                int row1 = row0 + 8;
                bool c1 = (col + 1 < N);
                if (Res) {
                    v0 += Res[(size_t)row0 * N + col];
                    if (c1) v1 += Res[(size_t)row0 * N + col + 1];
                    v2 += Res[(size_t)row1 * N + col];
                    if (c1) v3 += Res[(size_t)row1 * N + col + 1];
                }
                C[(size_t)row0 * N + col] = v0;
                if (c1) C[(size_t)row0 * N + col + 1] = v1;
                C[(size_t)row1 * N + col] = v2;
                if (c1) C[(size_t)row1 * N + col + 1] = v3;
            }
        }
    }
}

// ---------------- stage 3: causal depthwise conv (K=4) + SiLU + split ----------------
__global__ __launch_bounds__(128) void conv_kernel(
    const float* __restrict__ conv_w, const float* __restrict__ conv_b) {
    int c = blockIdx.x * 128 + threadIdx.x;
    int t0 = blockIdx.y * 64;
    float w0 = conv_w[c * 4 + 0], w1 = conv_w[c * 4 + 1];
    float w2 = conv_w[c * 4 + 2], w3 = conv_w[c * 4 + 3];
    float bias = conv_b[c];
    const float* col = g_proj + INTER + c;
    float h0, h1, h2;
    if ((t0 & (SEQ - 1)) == 0) {
        h0 = h1 = h2 = 0.f;
    } else {
        h0 = col[(size_t)(t0 - 3) * PROJ_DIM];
        h1 = col[(size_t)(t0 - 2) * PROJ_DIM];
        h2 = col[(size_t)(t0 - 1) * PROJ_DIM];
    }
    for (int i = 0; i < 64; i++) {
        int t = t0 + i;
        float xc = col[(size_t)t * PROJ_DIM];
        float a = bias + w0 * h0 + w1 * h1 + w2 * h2 + w3 * xc;
        float v = a / (1.f + expf(-a));
        if (c < INTER)
            g_xs[(size_t)t * INTER + c] = v;
        else if (c < INTER + STATE)
            g_Bm[(size_t)t * STATE + (c - INTER)] = v;
        else
            g_Cm[(size_t)t * STATE + (c - INTER - STATE)] = v;
        h0 = h1; h1 = h2; h2 = xc;
    }
}

// ---------------- stage 4: dt / dA ----------------
__global__ __launch_bounds__(256) void dt_kernel(
    const float* __restrict__ dt_bias, const float* __restrict__ A_log) {
    int i = blockIdx.x * 256 + threadIdx.x;
    if (i >= NTOK * HEADS) return;
    int h = i & (HEADS - 1);
    int tok = i >> 6;
    float raw = g_proj[(size_t)tok * PROJ_DIM + INTER + CONV_DIM + h];
    float s = raw + dt_bias[h];
    float dtv = (s > 20.f) ? s : log1pf(expf(s));
    float Aval = -expf(A_log[h]);
    g_dt[i] = dtv;
    g_dA[i] = expf(dtv * Aval);
}

// ---------------- stage 5: selective scan (scalar, known-good) ----------------
__global__ __launch_bounds__(256) void scan_kernel(const float* __restrict__ Dv) {
    int h = blockIdx.x, b = blockIdx.y;
    int lane = threadIdx.x & 31, w = threadIdx.x >> 5;
    int pi = lane & 7, nc = lane >> 3;
    int p = w * 8 + pi;
    float st[32];
    #pragma unroll
    for (int i = 0; i < 32; i++) st[i] = 0.f;
    float Dh = Dv[h];
    size_t tokBase = (size_t)b * SEQ;
    const float* xp = g_xs + tokBase * INTER + h * HEADDIM + p;
    const float4* Bp = (const float4*)(g_Bm + tokBase * STATE + nc * 32);
    const float4* Cp = (const float4*)(g_Cm + tokBase * STATE + nc * 32);
    const float* dAp = g_dA + tokBase * HEADS + h;
    const float* dtp = g_dt + tokBase * HEADS + h;
    float* yo = g_y + tokBase * INTER + h * HEADDIM + p;

    for (int t = 0; t < SEQ; t++) {
        float dAv = dAp[(size_t)t * HEADS];
        float dtv = dtp[(size_t)t * HEADS];
        float xv = xp[(size_t)t * INTER];
        float xdt = xv * dtv;
        const float4* B4 = Bp + (size_t)t * (STATE / 4);
        const float4* C4 = Cp + (size_t)t * (STATE / 4);
        float y0 = 0.f, y1 = 0.f, y2 = 0.f, y3 = 0.f;
        #pragma unroll
        for (int j = 0; j < 8; j++) {
            float4 bv = B4[j];
            float4 cv = C4[j];
            float s0 = st[4 * j + 0] * dAv + xdt * bv.x; st[4 * j + 0] = s0; y0 += s0 * cv.x;
            float s1 = st[4 * j + 1] * dAv + xdt * bv.y; st[4 * j + 1] = s1; y1 += s1 * cv.y;
            float s2 = st[4 * j + 2] * dAv + xdt * bv.z; st[4 * j + 2] = s2; y2 += s2 * cv.z;
            float s3 = st[4 * j + 3] * dAv + xdt * bv.w; st[4 * j + 3] = s3; y3 += s3 * cv.w;
        }
        float ys = (y0 + y1) + (y2 + y3);
        ys += __shfl_xor_sync(0xffffffffu, ys, 8);
        ys += __shfl_xor_sync(0xffffffffu, ys, 16);
        if (nc == 0) yo[(size_t)t * INTER] = ys + Dh * xv;
    }
}

// ---------------- stage 6: gated rmsnorm (writes tf32-rounded) ----------------
__global__ __launch_bounds__(256) void gatenorm_kernel(const float* __restrict__ gnw) {
    int row = blockIdx.x;
    const float* yrow = g_y + (size_t)row * INTER;
    const float* grow = g_proj + (size_t)row * PROJ_DIM;
    float vals[16];
    float ss = 0.f;
    #pragma unroll
    for (int i = 0; i < 16; i++) {
        int idx = threadIdx.x + i * 256;
        float gt = grow[idx];
        float v = yrow[idx] * (gt / (1.f + expf(-gt)));
        vals[i] = v;
        ss += v * v;
    }
    float tot = block_reduce_sum(ss);
    float scale = rsqrtf(tot * (1.f / INTER) + EPSV);
    float* orow = g_yn + (size_t)row * INTER;
    #pragma unroll
    for (int i = 0; i < 16; i++) {
        int idx = threadIdx.x + i * 256;
        orow[idx] = __uint_as_float(f2tf(vals[i] * scale * gnw[idx]));
    }
}

// ---------------- launch ----------------
extern "C" void kernel_launch(void* const* d_in, const int* in_sizes, int n_in,
                              void* d_out, int out_size) {
    const float* hidden  = (const float*)d_in[0];
    const float* norm_w  = (const float*)d_in[1];
    const float* in_proj = (const float*)d_in[2];
    const float* conv_w  = (const float*)d_in[3];
    const float* conv_b  = (const float*)d_in[4];
    const float* dt_bias = (const float*)d_in[5];
    const float* A_log   = (const float*)d_in[6];
    const float* Dvec    = (const float*)d_in[7];
    const float* gnw     = (const float*)d_in[8];
    const float* out_w   = (const float*)d_in[9];

    float *p_xn, *p_proj, *p_yn, *p_wa, *p_wb;
    cudaGetSymbolAddress((void**)&p_xn, g_xn);
    cudaGetSymbolAddress((void**)&p_proj, g_proj);
    cudaGetSymbolAddress((void**)&p_yn, g_yn);
    cudaGetSymbolAddress((void**)&p_wa, g_wa);
    cudaGetSymbolAddress((void**)&p_wb, g_wb);

    cudaFuncSetAttribute(gemm_tf32_nt, cudaFuncAttributeMaxDynamicSharedMemorySize, GEMM_SMEM);

    int n4a = (PROJ_DIM * HID) / 4;
    tf32_cvt_kernel<<<(n4a + 255) / 256, 256>>>(in_proj, p_wa, n4a);
    int n4b = (HID * INTER) / 4;
    tf32_cvt_kernel<<<(n4b + 255) / 256, 256>>>(out_w, p_wb, n4b);

    rmsnorm_in_kernel<<<NTOK, 256>>>(hidden, norm_w);

    // in_proj: [4096,2048] x [8512,2048]^T -> [4096,8512]
    gemm_tf32_nt<<<dim3((PROJ_DIM + 127) / 128, NTOK / 128), 256, GEMM_SMEM>>>(
        p_xn, p_wa, p_proj, nullptr, NTOK, PROJ_DIM, HID);

    conv_kernel<<<dim3(CONV_DIM / 128, NTOK / 64), 128>>>(conv_w, conv_b);

    dt_kernel<<<(NTOK * HEADS) / 256, 256>>>(dt_bias, A_log);

    scan_kernel<<<dim3(HEADS, 2), 256>>>(Dvec);

    gatenorm_kernel<<<NTOK, 256>>>(gnw);

    // out_proj: [4096,4096] x [2048,4096]^T + residual -> [4096,2048]
    gemm_tf32_nt<<<dim3(HID / 128, NTOK / 128), 256, GEMM_SMEM>>>(
        p_yn, p_wb, (float*)d_out, hidden, NTOK, HID, INTER);
}

// round 6
// speedup vs baseline: 1.1640x; 1.0323x over previous
#include <cuda_runtime.h>
#include <cuda_bf16.h>
#include <cstdint>

#define HID 2048
#define STATE 128
#define HEADS 64
#define HEADDIM 64
#define INTER 4096
#define CONV_DIM 4352
#define PROJ_DIM 8512
#define NTOK 4096
#define SEQ 2048
#define EPSV 1e-5f

// ---------------- scratch (device globals: no cudaMalloc allowed) ----------------
__device__ float g_xn[(size_t)NTOK * HID];         // rmsnormed input, tf32-rounded
__device__ float g_proj[(size_t)NTOK * PROJ_DIM];  // in_proj output
__device__ float g_xs[(size_t)NTOK * INTER];       // conv+silu x
__device__ float g_Bm[(size_t)NTOK * STATE];
__device__ float g_Cm[(size_t)NTOK * STATE];
__device__ float g_dt[(size_t)NTOK * HEADS];
__device__ float g_dA[(size_t)NTOK * HEADS];
__device__ float g_y[(size_t)NTOK * INTER];        // scan output
__device__ float g_yn[(size_t)NTOK * INTER];       // gated-norm output, tf32-rounded
__device__ float g_wa[(size_t)PROJ_DIM * HID];     // in_proj weights, tf32-rounded
__device__ float g_wb[(size_t)HID * INTER];        // out_proj weights, tf32-rounded

// ---------------- helpers ----------------
__device__ __forceinline__ uint32_t f2tf(float f) {
    uint32_t r;
    asm("cvt.rna.tf32.f32 %0, %1;" : "=r"(r) : "f"(f));
    return r;
}

__device__ __forceinline__ uint32_t smem_u32(const void* p) {
    uint32_t a;
    asm("{ .reg .u64 t; cvta.to.shared.u64 t, %1; cvt.u32.u64 %0, t; }" : "=r"(a) : "l"(p));
    return a;
}

#define CP_ASYNC16(saddr, gptr) \
    asm volatile("cp.async.cg.shared.global [%0], [%1], 16;" :: "r"(saddr), "l"(gptr) : "memory")
#define CP_COMMIT() asm volatile("cp.async.commit_group;" ::: "memory")
#define CP_WAIT2()  asm volatile("cp.async.wait_group 2;" ::: "memory")

__device__ __forceinline__ float fast_silu(float a) {
    return __fdividef(a, 1.f + __expf(-a));
}

__device__ __forceinline__ float block_reduce_sum(float v) {
    __shared__ float sh[32];
    int lane = threadIdx.x & 31, w = threadIdx.x >> 5;
    #pragma unroll
    for (int o = 16; o; o >>= 1) v += __shfl_xor_sync(0xffffffffu, v, o);
    if (lane == 0) sh[w] = v;
    __syncthreads();
    int nw = blockDim.x >> 5;
    float t = (threadIdx.x < (unsigned)nw) ? sh[threadIdx.x] : 0.f;
    if (w == 0) {
        #pragma unroll
        for (int o = 16; o; o >>= 1) t += __shfl_xor_sync(0xffffffffu, t, o);
        if (lane == 0) sh[0] = t;
    }
    __syncthreads();
    return sh[0];
}

// f32x2 packed math
typedef unsigned long long ull;
__device__ __forceinline__ ull pack2(float lo, float hi) {
    ull r; asm("mov.b64 %0, {%1,%2};" : "=l"(r) : "f"(lo), "f"(hi)); return r;
}
__device__ __forceinline__ ull mul2(ull a, ull b) {
    ull r; asm("mul.rn.f32x2 %0, %1, %2;" : "=l"(r) : "l"(a), "l"(b)); return r;
}
__device__ __forceinline__ ull fma2(ull a, ull b, ull c) {
    ull r; asm("fma.rn.f32x2 %0, %1, %2, %3;" : "=l"(r) : "l"(a), "l"(b), "l"(c)); return r;
}
__device__ __forceinline__ void unpack2(ull v, float& lo, float& hi) {
    asm("mov.b64 {%0,%1}, %2;" : "=f"(lo), "=f"(hi) : "l"(v));
}

// ---------------- stage 0: convert weights to tf32 bits ----------------
__global__ __launch_bounds__(256) void tf32_cvt_kernel(
    const float* __restrict__ in, float* __restrict__ out, int n4) {
    int i = blockIdx.x * 256 + threadIdx.x;
    if (i >= n4) return;
    float4 v = ((const float4*)in)[i];
    uint4 u;
    u.x = f2tf(v.x); u.y = f2tf(v.y); u.z = f2tf(v.z); u.w = f2tf(v.w);
    ((uint4*)out)[i] = u;
}

// ---------------- stage 1: input rmsnorm (writes tf32-rounded) ----------------
__global__ __launch_bounds__(256) void rmsnorm_in_kernel(
    const float* __restrict__ x, const float* __restrict__ w) {
    int row = blockIdx.x;
    const float* xr = x + (size_t)row * HID;
    float vals[8];
    float ss = 0.f;
    #pragma unroll
    for (int i = 0; i < 8; i++) {
        int idx = threadIdx.x + i * 256;
        float v = xr[idx];
        vals[i] = v;
        ss += v * v;
    }
    float tot = block_reduce_sum(ss);
    float scale = rsqrtf(tot * (1.f / HID) + EPSV);
    float* orow = g_xn + (size_t)row * HID;
    #pragma unroll
    for (int i = 0; i < 8; i++) {
        int idx = threadIdx.x + i * 256;
        orow[idx] = __uint_as_float(f2tf(vals[i] * scale * w[idx]));
    }
}

// ---------------- TF32 NT GEMM, cp.async 3-stage, 2 CTA/SM ----------------
#define BK 32
#define LDK 36
#define STAGE_FLOATS (128 * LDK)
#define GEMM_SMEM (3 * 2 * STAGE_FLOATS * 4)   // 110592 B

__global__ __launch_bounds__(256, 2) void gemm_tf32_nt(
    const float* __restrict__ A, const float* __restrict__ Bw,
    float* __restrict__ C, const float* __restrict__ Res,
    int M, int N, int K) {
    extern __shared__ float smf[];
    float* As = smf;                       // [3][128][LDK]
    float* Bs = smf + 3 * STAGE_FLOATS;
    uint32_t sA = smem_u32(As), sB = smem_u32(Bs);

    int tid = threadIdx.x;
    int mBase = blockIdx.y * 128, nBase = blockIdx.x * 128;
    int wid = tid >> 5, lane = tid & 31;
    int wm = wid >> 2, wn = wid & 3;     // 2 x 4 warps, warptile 64x32
    int g = lane >> 2, tg = lane & 3;
    int nk = K / BK;

    float acc[4][4][4];
    #pragma unroll
    for (int a = 0; a < 4; a++)
        #pragma unroll
        for (int b = 0; b < 4; b++)
            #pragma unroll
            for (int c = 0; c < 4; c++) acc[a][b][c] = 0.f;

    auto issue_tile = [&](int kt, int s) {
        size_t gk = (size_t)kt * BK;
        #pragma unroll
        for (int i = 0; i < 4; i++) {
            int idx = tid + i * 256;
            int row = idx >> 3, c4 = (idx & 7) * 4;
            uint32_t sa = sA + (uint32_t)(s * STAGE_FLOATS + row * LDK + c4) * 4u;
            CP_ASYNC16(sa, A + (size_t)(mBase + row) * K + gk + c4);
        }
        #pragma unroll
        for (int i = 0; i < 4; i++) {
            int idx = tid + i * 256;
            int row = idx >> 3, c4 = (idx & 7) * 4;
            if (nBase + row < N) {
                uint32_t sb2 = sB + (uint32_t)(s * STAGE_FLOATS + row * LDK + c4) * 4u;
                CP_ASYNC16(sb2, Bw + (size_t)(nBase + row) * K + gk + c4);
            }
        }
        CP_COMMIT();
    };

    issue_tile(0, 0);
    issue_tile(1, 1);

    int s_next = 2;
    for (int kt = 0; kt < nk; ++kt) {
        if (kt + 2 < nk) {
            issue_tile(kt + 2, s_next);
        } else {
            CP_COMMIT();
        }
        s_next++; if (s_next == 3) s_next = 0;
        CP_WAIT2();
        __syncthreads();

        int cur = kt % 3;
        const float* a_st = As + cur * STAGE_FLOATS;
        const float* b_st = Bs + cur * STAGE_FLOATS;
        #pragma unroll
        for (int kk = 0; kk < 4; ++kk) {
            uint32_t af[4][4], bf[4][2];
            int col = kk * 8 + tg;
            #pragma unroll
            for (int mt = 0; mt < 4; ++mt) {
                int row = wm * 64 + mt * 16 + g;
                af[mt][0] = __float_as_uint(a_st[row * LDK + col]);
                af[mt][1] = __float_as_uint(a_st[(row + 8) * LDK + col]);
                af[mt][2] = __float_as_uint(a_st[row * LDK + col + 4]);
                af[mt][3] = __float_as_uint(a_st[(row + 8) * LDK + col + 4]);
            }
            #pragma unroll
            for (int nt = 0; nt < 4; ++nt) {
                int nrow = wn * 32 + nt * 8 + g;
                bf[nt][0] = __float_as_uint(b_st[nrow * LDK + col]);
                bf[nt][1] = __float_as_uint(b_st[nrow * LDK + col + 4]);
            }
            #pragma unroll
            for (int mt = 0; mt < 4; ++mt)
                #pragma unroll
                for (int nt = 0; nt < 4; ++nt) {
                    asm volatile(
                        "mma.sync.aligned.m16n8k8.row.col.f32.tf32.tf32.f32 "
                        "{%0,%1,%2,%3},{%4,%5,%6,%7},{%8,%9},{%0,%1,%2,%3};\n"
                        : "+f"(acc[mt][nt][0]), "+f"(acc[mt][nt][1]),
                          "+f"(acc[mt][nt][2]), "+f"(acc[mt][nt][3])
                        : "r"(af[mt][0]), "r"(af[mt][1]), "r"(af[mt][2]), "r"(af[mt][3]),
                          "r"(bf[nt][0]), "r"(bf[nt][1]));
                }
        }
        __syncthreads();
    }

    // epilogue
    #pragma unroll
    for (int mt = 0; mt < 4; ++mt) {
        int row0 = mBase + wm * 64 + mt * 16 + g;
        #pragma unroll
        for (int nt = 0; nt < 4; ++nt) {
            int col = nBase + wn * 32 + nt * 8 + tg * 2;
            if (col < N) {
                float v0 = acc[mt][nt][0];
                float v1 = acc[mt][nt][1];
                float v2 = acc[mt][nt][2];
                float v3 = acc[mt][nt][3];
                int row1 = row0 + 8;
                bool c1 = (col + 1 < N);
                if (Res) {
                    v0 += Res[(size_t)row0 * N + col];
                    if (c1) v1 += Res[(size_t)row0 * N + col + 1];
                    v2 += Res[(size_t)row1 * N + col];
                    if (c1) v3 += Res[(size_t)row1 * N + col + 1];
                }
                C[(size_t)row0 * N + col] = v0;
                if (c1) C[(size_t)row0 * N + col + 1] = v1;
                C[(size_t)row1 * N + col] = v2;
                if (c1) C[(size_t)row1 * N + col + 1] = v3;
            }
        }
    }
}

// ---------------- stage 3: causal depthwise conv (K=4) + SiLU + split ----------------
__global__ __launch_bounds__(128) void conv_kernel(
    const float* __restrict__ conv_w, const float* __restrict__ conv_b) {
    int c = blockIdx.x * 128 + threadIdx.x;
    int t0 = blockIdx.y * 64;
    float w0 = conv_w[c * 4 + 0], w1 = conv_w[c * 4 + 1];
    float w2 = conv_w[c * 4 + 2], w3 = conv_w[c * 4 + 3];
    float bias = conv_b[c];
    const float* col = g_proj + INTER + c;
    float h0, h1, h2;
    if ((t0 & (SEQ - 1)) == 0) {
        h0 = h1 = h2 = 0.f;
    } else {
        h0 = col[(size_t)(t0 - 3) * PROJ_DIM];
        h1 = col[(size_t)(t0 - 2) * PROJ_DIM];
        h2 = col[(size_t)(t0 - 1) * PROJ_DIM];
    }
    for (int i = 0; i < 64; i++) {
        int t = t0 + i;
        float xc = col[(size_t)t * PROJ_DIM];
        float a = bias + w0 * h0 + w1 * h1 + w2 * h2 + w3 * xc;
        float v = fast_silu(a);
        if (c < INTER)
            g_xs[(size_t)t * INTER + c] = v;
        else if (c < INTER + STATE)
            g_Bm[(size_t)t * STATE + (c - INTER)] = v;
        else
            g_Cm[(size_t)t * STATE + (c - INTER - STATE)] = v;
        h0 = h1; h1 = h2; h2 = xc;
    }
}

// ---------------- stage 4: dt / dA ----------------
__global__ __launch_bounds__(256) void dt_kernel(
    const float* __restrict__ dt_bias, const float* __restrict__ A_log) {
    int i = blockIdx.x * 256 + threadIdx.x;
    if (i >= NTOK * HEADS) return;
    int h = i & (HEADS - 1);
    int tok = i >> 6;
    float raw = g_proj[(size_t)tok * PROJ_DIM + INTER + CONV_DIM + h];
    float s = raw + dt_bias[h];
    float dtv = (s > 20.f) ? s : log1pf(expf(s));
    float Aval = -expf(A_log[h]);
    g_dt[i] = dtv;
    g_dA[i] = expf(dtv * Aval);
}

// ---------------- stage 5: selective scan (f32x2 packed, stride fixed) ----------------
__global__ __launch_bounds__(256) void scan_kernel(const float* __restrict__ Dv) {
    int h = blockIdx.x, b = blockIdx.y;
    int lane = threadIdx.x & 31, w = threadIdx.x >> 5;
    int pi = lane & 7, nc = lane >> 3;
    int p = w * 8 + pi;
    ull st2[16];
    #pragma unroll
    for (int i = 0; i < 16; i++) st2[i] = 0ull;
    float Dh = Dv[h];
    size_t tokBase = (size_t)b * SEQ;
    const float* xp = g_xs + tokBase * INTER + h * HEADDIM + p;
    const ulonglong2* Bp = (const ulonglong2*)(g_Bm + tokBase * STATE + nc * 32);
    const ulonglong2* Cp = (const ulonglong2*)(g_Cm + tokBase * STATE + nc * 32);
    const float* dAp = g_dA + tokBase * HEADS + h;
    const float* dtp = g_dt + tokBase * HEADS + h;
    float* yo = g_y + tokBase * INTER + h * HEADDIM + p;

    for (int t = 0; t < SEQ; t++) {
        float dAv = dAp[(size_t)t * HEADS];
        float dtv = dtp[(size_t)t * HEADS];
        float xv = xp[(size_t)t * INTER];
        float xdt = xv * dtv;
        ull dA2 = pack2(dAv, dAv);
        ull xdt2 = pack2(xdt, xdt);
        // one token row = STATE floats = STATE/4 ulonglong2 (16B each)
        const ulonglong2* B4 = Bp + (size_t)t * (STATE / 4);
        const ulonglong2* C4 = Cp + (size_t)t * (STATE / 4);
        ull y2 = pack2(0.f, 0.f);
        #pragma unroll
        for (int j = 0; j < 8; j++) {
            ulonglong2 bv = B4[j];
            ulonglong2 cv = C4[j];
            st2[2 * j]     = fma2(st2[2 * j],     dA2, mul2(xdt2, bv.x));
            y2             = fma2(st2[2 * j],     cv.x, y2);
            st2[2 * j + 1] = fma2(st2[2 * j + 1], dA2, mul2(xdt2, bv.y));
            y2             = fma2(st2[2 * j + 1], cv.y, y2);
        }
        float ylo, yhi;
        unpack2(y2, ylo, yhi);
        float ys = ylo + yhi;
        ys += __shfl_xor_sync(0xffffffffu, ys, 8);
        ys += __shfl_xor_sync(0xffffffffu, ys, 16);
        if (nc == 0) yo[(size_t)t * INTER] = ys + Dh * xv;
    }
}

// ---------------- stage 6: gated rmsnorm (writes tf32-rounded) ----------------
__global__ __launch_bounds__(256) void gatenorm_kernel(const float* __restrict__ gnw) {
    int row = blockIdx.x;
    const float* yrow = g_y + (size_t)row * INTER;
    const float* grow = g_proj + (size_t)row * PROJ_DIM;
    float vals[16];
    float ss = 0.f;
    #pragma unroll
    for (int i = 0; i < 16; i++) {
        int idx = threadIdx.x + i * 256;
        float gt = grow[idx];
        float v = yrow[idx] * fast_silu(gt);
        vals[i] = v;
        ss += v * v;
    }
    float tot = block_reduce_sum(ss);
    float scale = rsqrtf(tot * (1.f / INTER) + EPSV);
    float* orow = g_yn + (size_t)row * INTER;
    #pragma unroll
    for (int i = 0; i < 16; i++) {
        int idx = threadIdx.x + i * 256;
        orow[idx] = __uint_as_float(f2tf(vals[i] * scale * gnw[idx]));
    }
}

// ---------------- launch ----------------
extern "C" void kernel_launch(void* const* d_in, const int* in_sizes, int n_in,
                              void* d_out, int out_size) {
    const float* hidden  = (const float*)d_in[0];
    const float* norm_w  = (const float*)d_in[1];
    const float* in_proj = (const float*)d_in[2];
    const float* conv_w  = (const float*)d_in[3];
    const float* conv_b  = (const float*)d_in[4];
    const float* dt_bias = (const float*)d_in[5];
    const float* A_log   = (const float*)d_in[6];
    const float* Dvec    = (const float*)d_in[7];
    const float* gnw     = (const float*)d_in[8];
    const float* out_w   = (const float*)d_in[9];

    float *p_xn, *p_proj, *p_yn, *p_wa, *p_wb;
    cudaGetSymbolAddress((void**)&p_xn, g_xn);
    cudaGetSymbolAddress((void**)&p_proj, g_proj);
    cudaGetSymbolAddress((void**)&p_yn, g_yn);
    cudaGetSymbolAddress((void**)&p_wa, g_wa);
    cudaGetSymbolAddress((void**)&p_wb, g_wb);

    cudaFuncSetAttribute(gemm_tf32_nt, cudaFuncAttributeMaxDynamicSharedMemorySize, GEMM_SMEM);

    int n4a = (PROJ_DIM * HID) / 4;
    tf32_cvt_kernel<<<(n4a + 255) / 256, 256>>>(in_proj, p_wa, n4a);
    int n4b = (HID * INTER) / 4;
    tf32_cvt_kernel<<<(n4b + 255) / 256, 256>>>(out_w, p_wb, n4b);

    rmsnorm_in_kernel<<<NTOK, 256>>>(hidden, norm_w);

    gemm_tf32_nt<<<dim3((PROJ_DIM + 127) / 128, NTOK / 128), 256, GEMM_SMEM>>>(
        p_xn, p_wa, p_proj, nullptr, NTOK, PROJ_DIM, HID);

    conv_kernel<<<dim3(CONV_DIM / 128, NTOK / 64), 128>>>(conv_w, conv_b);

    dt_kernel<<<(NTOK * HEADS) / 256, 256>>>(dt_bias, A_log);

    scan_kernel<<<dim3(HEADS, 2), 256>>>(Dvec);

    gatenorm_kernel<<<NTOK, 256>>>(gnw);

    gemm_tf32_nt<<<dim3(HID / 128, NTOK / 128), 256, GEMM_SMEM>>>(
        p_yn, p_wb, (float*)d_out, hidden, NTOK, HID, INTER);
}

// round 7
// speedup vs baseline: 1.6156x; 1.3880x over previous
#include <cuda_runtime.h>
#include <cuda_bf16.h>
#include <cstdint>

#define HID 2048
#define STATE 128
#define HEADS 64
#define HEADDIM 64
#define INTER 4096
#define CONV_DIM 4352
#define PROJ_DIM 8512
#define NTOK 4096
#define SEQ 2048
#define EPSV 1e-5f

// ---------------- scratch ----------------
__device__ float g_xn[(size_t)NTOK * HID];
__device__ float g_proj[(size_t)NTOK * PROJ_DIM];
__device__ float g_xs[(size_t)NTOK * INTER];
__device__ float g_Bm[(size_t)NTOK * STATE];
__device__ float g_Cm[(size_t)NTOK * STATE];
__device__ float g_dt[(size_t)NTOK * HEADS];
__device__ float g_dA[(size_t)NTOK * HEADS];
__device__ float g_y[(size_t)NTOK * INTER];
__device__ float g_yn[(size_t)NTOK * INTER];
__device__ float g_wa[(size_t)PROJ_DIM * HID];
__device__ float g_wb[(size_t)HID * INTER];

// ---------------- helpers ----------------
__device__ __forceinline__ uint32_t f2tf(float f) {
    uint32_t r;
    asm("cvt.rna.tf32.f32 %0, %1;" : "=r"(r) : "f"(f));
    return r;
}

__device__ __forceinline__ uint32_t smem_u32(const void* p) {
    uint32_t a;
    asm("{ .reg .u64 t; cvta.to.shared.u64 t, %1; cvt.u32.u64 %0, t; }" : "=r"(a) : "l"(p));
    return a;
}

#define CP_ASYNC16(saddr, gptr) \
    asm volatile("cp.async.cg.shared.global [%0], [%1], 16;" :: "r"(saddr), "l"(gptr) : "memory")
#define CP_COMMIT() asm volatile("cp.async.commit_group;" ::: "memory")
#define CP_WAIT2()  asm volatile("cp.async.wait_group 2;" ::: "memory")

__device__ __forceinline__ float fast_silu(float a) {
    return __fdividef(a, 1.f + __expf(-a));
}

__device__ __forceinline__ float block_reduce_sum(float v) {
    __shared__ float sh[32];
    int lane = threadIdx.x & 31, w = threadIdx.x >> 5;
    #pragma unroll
    for (int o = 16; o; o >>= 1) v += __shfl_xor_sync(0xffffffffu, v, o);
    if (lane == 0) sh[w] = v;
    __syncthreads();
    int nw = blockDim.x >> 5;
    float t = (threadIdx.x < (unsigned)nw) ? sh[threadIdx.x] : 0.f;
    if (w == 0) {
        #pragma unroll
        for (int o = 16; o; o >>= 1) t += __shfl_xor_sync(0xffffffffu, t, o);
        if (lane == 0) sh[0] = t;
    }
    __syncthreads();
    return sh[0];
}

// f32x2 packed math
typedef unsigned long long ull;
__device__ __forceinline__ ull pack2(float lo, float hi) {
    ull r; asm("mov.b64 %0, {%1,%2};" : "=l"(r) : "f"(lo), "f"(hi)); return r;
}
__device__ __forceinline__ ull mul2(ull a, ull b) {
    ull r; asm("mul.rn.f32x2 %0, %1, %2;" : "=l"(r) : "l"(a), "l"(b)); return r;
}
__device__ __forceinline__ ull fma2(ull a, ull b, ull c) {
    ull r; asm("fma.rn.f32x2 %0, %1, %2, %3;" : "=l"(r) : "l"(a), "l"(b), "l"(c)); return r;
}
__device__ __forceinline__ void unpack2(ull v, float& lo, float& hi) {
    asm("mov.b64 {%0,%1}, %2;" : "=f"(lo), "=f"(hi) : "l"(v));
}

// ---------------- stage 0: convert weights to tf32 bits ----------------
__global__ __launch_bounds__(256) void tf32_cvt_kernel(
    const float* __restrict__ in, float* __restrict__ out, int n4) {
    int i = blockIdx.x * 256 + threadIdx.x;
    if (i >= n4) return;
    float4 v = ((const float4*)in)[i];
    uint4 u;
    u.x = f2tf(v.x); u.y = f2tf(v.y); u.z = f2tf(v.z); u.w = f2tf(v.w);
    ((uint4*)out)[i] = u;
}

// ---------------- stage 1: input rmsnorm ----------------
__global__ __launch_bounds__(256) void rmsnorm_in_kernel(
    const float* __restrict__ x, const float* __restrict__ w) {
    int row = blockIdx.x;
    const float* xr = x + (size_t)row * HID;
    float vals[8];
    float ss = 0.f;
    #pragma unroll
    for (int i = 0; i < 8; i++) {
        int idx = threadIdx.x + i * 256;
        float v = xr[idx];
        vals[i] = v;
        ss += v * v;
    }
    float tot = block_reduce_sum(ss);
    float scale = rsqrtf(tot * (1.f / HID) + EPSV);
    float* orow = g_xn + (size_t)row * HID;
    #pragma unroll
    for (int i = 0; i < 8; i++) {
        int idx = threadIdx.x + i * 256;
        orow[idx] = __uint_as_float(f2tf(vals[i] * scale * w[idx]));
    }
}

// ---------------- TF32 NT GEMM: 128 threads, warptile 64x64, 3-stage ----------------
#define BK 32
#define LDK 36
#define STAGE_FLOATS (128 * LDK)
#define GEMM_SMEM (3 * 2 * STAGE_FLOATS * 4)   // 110592 B

__global__ __launch_bounds__(128, 2) void gemm_tf32_nt(
    const float* __restrict__ A, const float* __restrict__ Bw,
    float* __restrict__ C, const float* __restrict__ Res,
    int M, int N, int K) {
    extern __shared__ float smf[];
    float* As = smf;                       // [3][128][LDK]
    float* Bs = smf + 3 * STAGE_FLOATS;
    uint32_t sA = smem_u32(As), sB = smem_u32(Bs);

    int tid = threadIdx.x;
    int mBase = blockIdx.y * 128, nBase = blockIdx.x * 128;
    int wid = tid >> 5, lane = tid & 31;
    int wm = wid >> 1, wn = wid & 1;     // 2 x 2 warps, warptile 64x64
    int g = lane >> 2, tg = lane & 3;
    int nk = K / BK;

    float acc[4][8][4];
    #pragma unroll
    for (int a = 0; a < 4; a++)
        #pragma unroll
        for (int b = 0; b < 8; b++)
            #pragma unroll
            for (int c = 0; c < 4; c++) acc[a][b][c] = 0.f;

    auto issue_tile = [&](int kt, int s) {
        size_t gk = (size_t)kt * BK;
        #pragma unroll
        for (int i = 0; i < 8; i++) {
            int idx = tid + i * 128;
            int row = idx >> 3, c4 = (idx & 7) * 4;
            uint32_t sa = sA + (uint32_t)(s * STAGE_FLOATS + row * LDK + c4) * 4u;
            CP_ASYNC16(sa, A + (size_t)(mBase + row) * K + gk + c4);
        }
        #pragma unroll
        for (int i = 0; i < 8; i++) {
            int idx = tid + i * 128;
            int row = idx >> 3, c4 = (idx & 7) * 4;
            if (nBase + row < N) {
                uint32_t sb2 = sB + (uint32_t)(s * STAGE_FLOATS + row * LDK + c4) * 4u;
                CP_ASYNC16(sb2, Bw + (size_t)(nBase + row) * K + gk + c4);
            }
        }
        CP_COMMIT();
    };

    issue_tile(0, 0);
    issue_tile(1, 1);

    int s_next = 2;
    for (int kt = 0; kt < nk; ++kt) {
        if (kt + 2 < nk) {
            issue_tile(kt + 2, s_next);
        } else {
            CP_COMMIT();
        }
        s_next++; if (s_next == 3) s_next = 0;
        CP_WAIT2();
        __syncthreads();

        int cur = kt % 3;
        const float* a_st = As + cur * STAGE_FLOATS;
        const float* b_st = Bs + cur * STAGE_FLOATS;
        #pragma unroll
        for (int kk = 0; kk < 4; ++kk) {
            uint32_t af[4][4], bf[8][2];
            int col = kk * 8 + tg;
            #pragma unroll
            for (int mt = 0; mt < 4; ++mt) {
                int row = wm * 64 + mt * 16 + g;
                af[mt][0] = __float_as_uint(a_st[row * LDK + col]);
                af[mt][1] = __float_as_uint(a_st[(row + 8) * LDK + col]);
                af[mt][2] = __float_as_uint(a_st[row * LDK + col + 4]);
                af[mt][3] = __float_as_uint(a_st[(row + 8) * LDK + col + 4]);
            }
            #pragma unroll
            for (int nt = 0; nt < 8; ++nt) {
                int nrow = wn * 64 + nt * 8 + g;
                bf[nt][0] = __float_as_uint(b_st[nrow * LDK + col]);
                bf[nt][1] = __float_as_uint(b_st[nrow * LDK + col + 4]);
            }
            #pragma unroll
            for (int mt = 0; mt < 4; ++mt)
                #pragma unroll
                for (int nt = 0; nt < 8; ++nt) {
                    asm volatile(
                        "mma.sync.aligned.m16n8k8.row.col.f32.tf32.tf32.f32 "
                        "{%0,%1,%2,%3},{%4,%5,%6,%7},{%8,%9},{%0,%1,%2,%3};\n"
                        : "+f"(acc[mt][nt][0]), "+f"(acc[mt][nt][1]),
                          "+f"(acc[mt][nt][2]), "+f"(acc[mt][nt][3])
                        : "r"(af[mt][0]), "r"(af[mt][1]), "r"(af[mt][2]), "r"(af[mt][3]),
                          "r"(bf[nt][0]), "r"(bf[nt][1]));
                }
        }
        __syncthreads();
    }

    // epilogue
    #pragma unroll
    for (int mt = 0; mt < 4; ++mt) {
        int row0 = mBase + wm * 64 + mt * 16 + g;
        #pragma unroll
        for (int nt = 0; nt < 8; ++nt) {
            int col = nBase + wn * 64 + nt * 8 + tg * 2;
            if (col < N) {
                float v0 = acc[mt][nt][0];
                float v1 = acc[mt][nt][1];
                float v2 = acc[mt][nt][2];
                float v3 = acc[mt][nt][3];
                int row1 = row0 + 8;
                bool c1 = (col + 1 < N);
                if (Res) {
                    v0 += Res[(size_t)row0 * N + col];
                    if (c1) v1 += Res[(size_t)row0 * N + col + 1];
                    v2 += Res[(size_t)row1 * N + col];
                    if (c1) v3 += Res[(size_t)row1 * N + col + 1];
                }
                C[(size_t)row0 * N + col] = v0;
                if (c1) C[(size_t)row0 * N + col + 1] = v1;
                C[(size_t)row1 * N + col] = v2;
                if (c1) C[(size_t)row1 * N + col + 1] = v3;
            }
        }
    }
}

// ---------------- stage 3: causal depthwise conv (K=4) + SiLU + split ----------------
__global__ __launch_bounds__(128) void conv_kernel(
    const float* __restrict__ conv_w, const float* __restrict__ conv_b) {
    int c = blockIdx.x * 128 + threadIdx.x;
    int t0 = blockIdx.y * 64;
    float w0 = conv_w[c * 4 + 0], w1 = conv_w[c * 4 + 1];
    float w2 = conv_w[c * 4 + 2], w3 = conv_w[c * 4 + 3];
    float bias = conv_b[c];
    const float* col = g_proj + INTER + c;
    float h0, h1, h2;
    if ((t0 & (SEQ - 1)) == 0) {
        h0 = h1 = h2 = 0.f;
    } else {
        h0 = col[(size_t)(t0 - 3) * PROJ_DIM];
        h1 = col[(size_t)(t0 - 2) * PROJ_DIM];
        h2 = col[(size_t)(t0 - 1) * PROJ_DIM];
    }
    for (int i = 0; i < 64; i++) {
        int t = t0 + i;
        float xc = col[(size_t)t * PROJ_DIM];
        float a = bias + w0 * h0 + w1 * h1 + w2 * h2 + w3 * xc;
        float v = fast_silu(a);
        if (c < INTER)
            g_xs[(size_t)t * INTER + c] = v;
        else if (c < INTER + STATE)
            g_Bm[(size_t)t * STATE + (c - INTER)] = v;
        else
            g_Cm[(size_t)t * STATE + (c - INTER - STATE)] = v;
        h0 = h1; h1 = h2; h2 = xc;
    }
}

// ---------------- stage 4: dt / dA ----------------
__global__ __launch_bounds__(256) void dt_kernel(
    const float* __restrict__ dt_bias, const float* __restrict__ A_log) {
    int i = blockIdx.x * 256 + threadIdx.x;
    if (i >= NTOK * HEADS) return;
    int h = i & (HEADS - 1);
    int tok = i >> 6;
    float raw = g_proj[(size_t)tok * PROJ_DIM + INTER + CONV_DIM + h];
    float s = raw + dt_bias[h];
    float dtv = (s > 20.f) ? s : log1pf(expf(s));
    float Aval = -expf(A_log[h]);
    g_dt[i] = dtv;
    g_dA[i] = expf(dtv * Aval);
}

// ---------------- stage 5: selective scan, smem-staged B/C ----------------
// block=(h,b), 256 thr. Chunks of 16 tokens double-buffered in smem.
#define TCH 16
__global__ __launch_bounds__(256) void scan_kernel(const float* __restrict__ Dv) {
    __shared__ float sBC[2][TCH][2 * STATE];   // [buf][t][B(128) | C(128)]  32KB
    int h = blockIdx.x, b = blockIdx.y;
    int tidx = threadIdx.x;
    int lane = tidx & 31, w = tidx >> 5;
    int pi = lane & 7, nc = lane >> 3;
    int p = w * 8 + pi;
    ull st2[16];
    #pragma unroll
    for (int i = 0; i < 16; i++) st2[i] = 0ull;
    float Dh = Dv[h];
    size_t tokBase = (size_t)b * SEQ;
    const float* xp = g_xs + tokBase * INTER + h * HEADDIM + p;
    const float4* Bg = (const float4*)(g_Bm + tokBase * STATE);   // 32 float4 per token
    const float4* Cg = (const float4*)(g_Cm + tokBase * STATE);
    const float* dAp = g_dA + tokBase * HEADS + h;
    const float* dtp = g_dt + tokBase * HEADS + h;
    float* yo = g_y + tokBase * INTER + h * HEADDIM + p;

    // loader mapping: 2 float4 per thread per matrix per chunk
    // f = tidx + j*256 (j<2): token tt = f>>5, quad q = f&31
    int lt0 = (tidx + 0) >> 5, lq0 = (tidx + 0) & 31;
    int lt1 = (tidx + 256) >> 5, lq1 = (tidx + 256) & 31;

    // prologue: load chunk 0 into buf 0
    {
        float4 b0 = Bg[(size_t)(0 + lt0) * 32 + lq0];
        float4 b1 = Bg[(size_t)(0 + lt1) * 32 + lq1];
        float4 c0 = Cg[(size_t)(0 + lt0) * 32 + lq0];
        float4 c1 = Cg[(size_t)(0 + lt1) * 32 + lq1];
        *(float4*)&sBC[0][lt0][lq0 * 4] = b0;
        *(float4*)&sBC[0][lt1][lq1 * 4] = b1;
        *(float4*)&sBC[0][lt0][STATE + lq0 * 4] = c0;
        *(float4*)&sBC[0][lt1][STATE + lq1 * 4] = c1;
    }
    __syncthreads();

    int nch = SEQ / TCH;
    for (int ck = 0; ck < nch; ck++) {
        int buf = ck & 1;
        // issue gmem loads for next chunk into registers (latency hidden by compute)
        float4 nb0, nb1, nc0, nc1;
        bool more = (ck + 1 < nch);
        if (more) {
            int t0 = (ck + 1) * TCH;
            nb0 = Bg[(size_t)(t0 + lt0) * 32 + lq0];
            nb1 = Bg[(size_t)(t0 + lt1) * 32 + lq1];
            nc0 = Cg[(size_t)(t0 + lt0) * 32 + lq0];
            nc1 = Cg[(size_t)(t0 + lt1) * 32 + lq1];
        }
        int tb = ck * TCH;
        #pragma unroll
        for (int ti = 0; ti < TCH; ti++) {
            int t = tb + ti;
            float dAv = dAp[(size_t)t * HEADS];
            float dtv = dtp[(size_t)t * HEADS];
            float xv = xp[(size_t)t * INTER];
            float xdt = xv * dtv;
            ull dA2 = pack2(dAv, dAv);
            ull xdt2 = pack2(xdt, xdt);
            const ulonglong2* B4 = (const ulonglong2*)&sBC[buf][ti][nc * 32];
            const ulonglong2* C4 = (const ulonglong2*)&sBC[buf][ti][STATE + nc * 32];
            ull y2 = pack2(0.f, 0.f);
            #pragma unroll
            for (int j = 0; j < 8; j++) {
                ulonglong2 bv = B4[j];
                ulonglong2 cv = C4[j];
                st2[2 * j]     = fma2(st2[2 * j],     dA2, mul2(xdt2, bv.x));
                y2             = fma2(st2[2 * j],     cv.x, y2);
                st2[2 * j + 1] = fma2(st2[2 * j + 1], dA2, mul2(xdt2, bv.y));
                y2             = fma2(st2[2 * j + 1], cv.y, y2);
            }
            float ylo, yhi;
            unpack2(y2, ylo, yhi);
            float ys = ylo + yhi;
            ys += __shfl_xor_sync(0xffffffffu, ys, 8);
            ys += __shfl_xor_sync(0xffffffffu, ys, 16);
            if (nc == 0) yo[(size_t)t * INTER] = ys + Dh * xv;
        }
        __syncthreads();
        if (more) {
            int nbuf = buf ^ 1;
            *(float4*)&sBC[nbuf][lt0][lq0 * 4] = nb0;
            *(float4*)&sBC[nbuf][lt1][lq1 * 4] = nb1;
            *(float4*)&sBC[nbuf][lt0][STATE + lq0 * 4] = nc0;
            *(float4*)&sBC[nbuf][lt1][STATE + lq1 * 4] = nc1;
            __syncthreads();
        }
    }
}

// ---------------- stage 6: gated rmsnorm ----------------
__global__ __launch_bounds__(256) void gatenorm_kernel(const float* __restrict__ gnw) {
    int row = blockIdx.x;
    const float* yrow = g_y + (size_t)row * INTER;
    const float* grow = g_proj + (size_t)row * PROJ_DIM;
    float vals[16];
    float ss = 0.f;
    #pragma unroll
    for (int i = 0; i < 16; i++) {
        int idx = threadIdx.x + i * 256;
        float gt = grow[idx];
        float v = yrow[idx] * fast_silu(gt);
        vals[i] = v;
        ss += v * v;
    }
    float tot = block_reduce_sum(ss);
    float scale = rsqrtf(tot * (1.f / INTER) + EPSV);
    float* orow = g_yn + (size_t)row * INTER;
    #pragma unroll
    for (int i = 0; i < 16; i++) {
        int idx = threadIdx.x + i * 256;
        orow[idx] = __uint_as_float(f2tf(vals[i] * scale * gnw[idx]));
    }
}

// ---------------- launch ----------------
extern "C" void kernel_launch(void* const* d_in, const int* in_sizes, int n_in,
                              void* d_out, int out_size) {
    const float* hidden  = (const float*)d_in[0];
    const float* norm_w  = (const float*)d_in[1];
    const float* in_proj = (const float*)d_in[2];
    const float* conv_w  = (const float*)d_in[3];
    const float* conv_b  = (const float*)d_in[4];
    const float* dt_bias = (const float*)d_in[5];
    const float* A_log   = (const float*)d_in[6];
    const float* Dvec    = (const float*)d_in[7];
    const float* gnw     = (const float*)d_in[8];
    const float* out_w   = (const float*)d_in[9];

    float *p_xn, *p_proj, *p_yn, *p_wa, *p_wb;
    cudaGetSymbolAddress((void**)&p_xn, g_xn);
    cudaGetSymbolAddress((void**)&p_proj, g_proj);
    cudaGetSymbolAddress((void**)&p_yn, g_yn);
    cudaGetSymbolAddress((void**)&p_wa, g_wa);
    cudaGetSymbolAddress((void**)&p_wb, g_wb);

    cudaFuncSetAttribute(gemm_tf32_nt, cudaFuncAttributeMaxDynamicSharedMemorySize, GEMM_SMEM);

    int n4a = (PROJ_DIM * HID) / 4;
    tf32_cvt_kernel<<<(n4a + 255) / 256, 256>>>(in_proj, p_wa, n4a);
    int n4b = (HID * INTER) / 4;
    tf32_cvt_kernel<<<(n4b + 255) / 256, 256>>>(out_w, p_wb, n4b);

    rmsnorm_in_kernel<<<NTOK, 256>>>(hidden, norm_w);

    gemm_tf32_nt<<<dim3((PROJ_DIM + 127) / 128, NTOK / 128), 128, GEMM_SMEM>>>(
        p_xn, p_wa, p_proj, nullptr, NTOK, PROJ_DIM, HID);

    conv_kernel<<<dim3(CONV_DIM / 128, NTOK / 64), 128>>>(conv_w, conv_b);

    dt_kernel<<<(NTOK * HEADS) / 256, 256>>>(dt_bias, A_log);

    scan_kernel<<<dim3(HEADS, 2), 256>>>(Dvec);

    gatenorm_kernel<<<NTOK, 256>>>(gnw);

    gemm_tf32_nt<<<dim3(HID / 128, NTOK / 128), 128, GEMM_SMEM>>>(
        p_yn, p_wb, (float*)d_out, hidden, NTOK, HID, INTER);
}

// round 8
// speedup vs baseline: 1.6217x; 1.0038x over previous
#include <cuda_runtime.h>
#include <cuda_bf16.h>
#include <cstdint>

#define HID 2048
#define STATE 128
#define HEADS 64
#define HEADDIM 64
#define INTER 4096
#define CONV_DIM 4352
#define PROJ_DIM 8512
#define NTOK 4096
#define SEQ 2048
#define EPSV 1e-5f

// ---------------- scratch ----------------
__device__ float g_xn[(size_t)NTOK * HID];
__device__ float g_proj[(size_t)NTOK * PROJ_DIM];
__device__ float g_xs[(size_t)NTOK * INTER];
__device__ float g_Bm[(size_t)NTOK * STATE];
__device__ float g_Cm[(size_t)NTOK * STATE];
__device__ float g_dt[(size_t)NTOK * HEADS];
__device__ float g_dA[(size_t)NTOK * HEADS];
__device__ float g_y[(size_t)NTOK * INTER];
__device__ float g_yn[(size_t)NTOK * INTER];
__device__ float g_wa[(size_t)PROJ_DIM * HID];
__device__ float g_wb[(size_t)HID * INTER];

// ---------------- helpers ----------------
__device__ __forceinline__ uint32_t f2tf(float f) {
    uint32_t r;
    asm("cvt.rna.tf32.f32 %0, %1;" : "=r"(r) : "f"(f));
    return r;
}

__device__ __forceinline__ uint32_t smem_u32(const void* p) {
    uint32_t a;
    asm("{ .reg .u64 t; cvta.to.shared.u64 t, %1; cvt.u32.u64 %0, t; }" : "=r"(a) : "l"(p));
    return a;
}

#define CP_ASYNC16(saddr, gptr) \
    asm volatile("cp.async.cg.shared.global [%0], [%1], 16;" :: "r"(saddr), "l"(gptr) : "memory")
#define CP_COMMIT() asm volatile("cp.async.commit_group;" ::: "memory")
#define CP_WAIT2()  asm volatile("cp.async.wait_group 2;" ::: "memory")

__device__ __forceinline__ float fast_silu(float a) {
    return __fdividef(a, 1.f + __expf(-a));
}

__device__ __forceinline__ float block_reduce_sum(float v) {
    __shared__ float sh[32];
    int lane = threadIdx.x & 31, w = threadIdx.x >> 5;
    #pragma unroll
    for (int o = 16; o; o >>= 1) v += __shfl_xor_sync(0xffffffffu, v, o);
    if (lane == 0) sh[w] = v;
    __syncthreads();
    int nw = blockDim.x >> 5;
    float t = (threadIdx.x < (unsigned)nw) ? sh[threadIdx.x] : 0.f;
    if (w == 0) {
        #pragma unroll
        for (int o = 16; o; o >>= 1) t += __shfl_xor_sync(0xffffffffu, t, o);
        if (lane == 0) sh[0] = t;
    }
    __syncthreads();
    return sh[0];
}

// f32x2 packed math
typedef unsigned long long ull;
__device__ __forceinline__ ull pack2(float lo, float hi) {
    ull r; asm("mov.b64 %0, {%1,%2};" : "=l"(r) : "f"(lo), "f"(hi)); return r;
}
__device__ __forceinline__ ull mul2(ull a, ull b) {
    ull r; asm("mul.rn.f32x2 %0, %1, %2;" : "=l"(r) : "l"(a), "l"(b)); return r;
}
__device__ __forceinline__ ull fma2(ull a, ull b, ull c) {
    ull r; asm("fma.rn.f32x2 %0, %1, %2, %3;" : "=l"(r) : "l"(a), "l"(b), "l"(c)); return r;
}
__device__ __forceinline__ void unpack2(ull v, float& lo, float& hi) {
    asm("mov.b64 {%0,%1}, %2;" : "=f"(lo), "=f"(hi) : "l"(v));
}

// ---------------- stage 0: convert weights to tf32 bits ----------------
__global__ __launch_bounds__(256) void tf32_cvt_kernel(
    const float* __restrict__ in, float* __restrict__ out, int n4) {
    int i = blockIdx.x * 256 + threadIdx.x;
    if (i >= n4) return;
    float4 v = ((const float4*)in)[i];
    uint4 u;
    u.x = f2tf(v.x); u.y = f2tf(v.y); u.z = f2tf(v.z); u.w = f2tf(v.w);
    ((uint4*)out)[i] = u;
}

// ---------------- stage 1: input rmsnorm ----------------
__global__ __launch_bounds__(256) void rmsnorm_in_kernel(
    const float* __restrict__ x, const float* __restrict__ w) {
    int row = blockIdx.x;
    const float* xr = x + (size_t)row * HID;
    float vals[8];
    float ss = 0.f;
    #pragma unroll
    for (int i = 0; i < 8; i++) {
        int idx = threadIdx.x + i * 256;
        float v = xr[idx];
        vals[i] = v;
        ss += v * v;
    }
    float tot = block_reduce_sum(ss);
    float scale = rsqrtf(tot * (1.f / HID) + EPSV);
    float* orow = g_xn + (size_t)row * HID;
    #pragma unroll
    for (int i = 0; i < 8; i++) {
        int idx = threadIdx.x + i * 256;
        orow[idx] = __uint_as_float(f2tf(vals[i] * scale * w[idx]));
    }
}

// ---------------- TF32 NT GEMM: 128 threads, warptile 64x64, 3-stage ----------------
#define BK 32
#define LDK 36
#define STAGE_FLOATS (128 * LDK)
#define GEMM_SMEM (3 * 2 * STAGE_FLOATS * 4)   // 110592 B

__global__ __launch_bounds__(128, 2) void gemm_tf32_nt(
    const float* __restrict__ A, const float* __restrict__ Bw,
    float* __restrict__ C, const float* __restrict__ Res,
    int M, int N, int K) {
    extern __shared__ float smf[];
    float* As = smf;                       // [3][128][LDK]
    float* Bs = smf + 3 * STAGE_FLOATS;
    uint32_t sA = smem_u32(As), sB = smem_u32(Bs);

    int tid = threadIdx.x;
    int mBase = blockIdx.y * 128, nBase = blockIdx.x * 128;
    int wid = tid >> 5, lane = tid & 31;
    int wm = wid >> 1, wn = wid & 1;     // 2 x 2 warps, warptile 64x64
    int g = lane >> 2, tg = lane & 3;
    int nk = K / BK;

    float acc[4][8][4];
    #pragma unroll
    for (int a = 0; a < 4; a++)
        #pragma unroll
        for (int b = 0; b < 8; b++)
            #pragma unroll
            for (int c = 0; c < 4; c++) acc[a][b][c] = 0.f;

    auto issue_tile = [&](int kt, int s) {
        size_t gk = (size_t)kt * BK;
        #pragma unroll
        for (int i = 0; i < 8; i++) {
            int idx = tid + i * 128;
            int row = idx >> 3, c4 = (idx & 7) * 4;
            uint32_t sa = sA + (uint32_t)(s * STAGE_FLOATS + row * LDK + c4) * 4u;
            CP_ASYNC16(sa, A + (size_t)(mBase + row) * K + gk + c4);
        }
        #pragma unroll
        for (int i = 0; i < 8; i++) {
            int idx = tid + i * 128;
            int row = idx >> 3, c4 = (idx & 7) * 4;
            if (nBase + row < N) {
                uint32_t sb2 = sB + (uint32_t)(s * STAGE_FLOATS + row * LDK + c4) * 4u;
                CP_ASYNC16(sb2, Bw + (size_t)(nBase + row) * K + gk + c4);
            }
        }
        CP_COMMIT();
    };

    issue_tile(0, 0);
    issue_tile(1, 1);

    int s_next = 2;
    for (int kt = 0; kt < nk; ++kt) {
        if (kt + 2 < nk) {
            issue_tile(kt + 2, s_next);
        } else {
            CP_COMMIT();
        }
        s_next++; if (s_next == 3) s_next = 0;
        CP_WAIT2();
        __syncthreads();

        int cur = kt % 3;
        const float* a_st = As + cur * STAGE_FLOATS;
        const float* b_st = Bs + cur * STAGE_FLOATS;
        #pragma unroll
        for (int kk = 0; kk < 4; ++kk) {
            uint32_t af[4][4], bf[8][2];
            int col = kk * 8 + tg;
            #pragma unroll
            for (int mt = 0; mt < 4; ++mt) {
                int row = wm * 64 + mt * 16 + g;
                af[mt][0] = __float_as_uint(a_st[row * LDK + col]);
                af[mt][1] = __float_as_uint(a_st[(row + 8) * LDK + col]);
                af[mt][2] = __float_as_uint(a_st[row * LDK + col + 4]);
                af[mt][3] = __float_as_uint(a_st[(row + 8) * LDK + col + 4]);
            }
            #pragma unroll
            for (int nt = 0; nt < 8; ++nt) {
                int nrow = wn * 64 + nt * 8 + g;
                bf[nt][0] = __float_as_uint(b_st[nrow * LDK + col]);
                bf[nt][1] = __float_as_uint(b_st[nrow * LDK + col + 4]);
            }
            #pragma unroll
            for (int mt = 0; mt < 4; ++mt)
                #pragma unroll
                for (int nt = 0; nt < 8; ++nt) {
                    asm volatile(
                        "mma.sync.aligned.m16n8k8.row.col.f32.tf32.tf32.f32 "
                        "{%0,%1,%2,%3},{%4,%5,%6,%7},{%8,%9},{%0,%1,%2,%3};\n"
                        : "+f"(acc[mt][nt][0]), "+f"(acc[mt][nt][1]),
                          "+f"(acc[mt][nt][2]), "+f"(acc[mt][nt][3])
                        : "r"(af[mt][0]), "r"(af[mt][1]), "r"(af[mt][2]), "r"(af[mt][3]),
                          "r"(bf[nt][0]), "r"(bf[nt][1]));
                }
        }
        __syncthreads();
    }

    // epilogue
    #pragma unroll
    for (int mt = 0; mt < 4; ++mt) {
        int row0 = mBase + wm * 64 + mt * 16 + g;
        #pragma unroll
        for (int nt = 0; nt < 8; ++nt) {
            int col = nBase + wn * 64 + nt * 8 + tg * 2;
            if (col < N) {
                float v0 = acc[mt][nt][0];
                float v1 = acc[mt][nt][1];
                float v2 = acc[mt][nt][2];
                float v3 = acc[mt][nt][3];
                int row1 = row0 + 8;
                bool c1 = (col + 1 < N);
                if (Res) {
                    v0 += Res[(size_t)row0 * N + col];
                    if (c1) v1 += Res[(size_t)row0 * N + col + 1];
                    v2 += Res[(size_t)row1 * N + col];
                    if (c1) v3 += Res[(size_t)row1 * N + col + 1];
                }
                C[(size_t)row0 * N + col] = v0;
                if (c1) C[(size_t)row0 * N + col + 1] = v1;
                C[(size_t)row1 * N + col] = v2;
                if (c1) C[(size_t)row1 * N + col + 1] = v3;
            }
        }
    }
}

// ---------------- stage 3: causal depthwise conv (K=4) + SiLU + split ----------------
__global__ __launch_bounds__(128) void conv_kernel(
    const float* __restrict__ conv_w, const float* __restrict__ conv_b) {
    int c = blockIdx.x * 128 + threadIdx.x;
    int t0 = blockIdx.y * 64;
    float w0 = conv_w[c * 4 + 0], w1 = conv_w[c * 4 + 1];
    float w2 = conv_w[c * 4 + 2], w3 = conv_w[c * 4 + 3];
    float bias = conv_b[c];
    const float* col = g_proj + INTER + c;
    float h0, h1, h2;
    if ((t0 & (SEQ - 1)) == 0) {
        h0 = h1 = h2 = 0.f;
    } else {
        h0 = col[(size_t)(t0 - 3) * PROJ_DIM];
        h1 = col[(size_t)(t0 - 2) * PROJ_DIM];
        h2 = col[(size_t)(t0 - 1) * PROJ_DIM];
    }
    for (int i = 0; i < 64; i++) {
        int t = t0 + i;
        float xc = col[(size_t)t * PROJ_DIM];
        float a = bias + w0 * h0 + w1 * h1 + w2 * h2 + w3 * xc;
        float v = fast_silu(a);
        if (c < INTER)
            g_xs[(size_t)t * INTER + c] = v;
        else if (c < INTER + STATE)
            g_Bm[(size_t)t * STATE + (c - INTER)] = v;
        else
            g_Cm[(size_t)t * STATE + (c - INTER - STATE)] = v;
        h0 = h1; h1 = h2; h2 = xc;
    }
}

// ---------------- stage 4: dt / dA ----------------
__global__ __launch_bounds__(256) void dt_kernel(
    const float* __restrict__ dt_bias, const float* __restrict__ A_log) {
    int i = blockIdx.x * 256 + threadIdx.x;
    if (i >= NTOK * HEADS) return;
    int h = i & (HEADS - 1);
    int tok = i >> 6;
    float raw = g_proj[(size_t)tok * PROJ_DIM + INTER + CONV_DIM + h];
    float s = raw + dt_bias[h];
    float dtv = (s > 20.f) ? s : log1pf(expf(s));
    float Aval = -expf(A_log[h]);
    g_dt[i] = dtv;
    g_dA[i] = expf(dtv * Aval);
}

// ---------------- stage 5: selective scan, smem-staged B/C ----------------
// block=(h,b), 256 thr. Chunks of 16 tokens double-buffered in smem.
#define TCH 16
__global__ __launch_bounds__(256) void scan_kernel(const float* __restrict__ Dv) {
    __shared__ float sBC[2][TCH][2 * STATE];   // [buf][t][B(128) | C(128)]  32KB
    int h = blockIdx.x, b = blockIdx.y;
    int tidx = threadIdx.x;
    int lane = tidx & 31, w = tidx >> 5;
    int pi = lane & 7, nc = lane >> 3;
    int p = w * 8 + pi;
    ull st2[16];
    #pragma unroll
    for (int i = 0; i < 16; i++) st2[i] = 0ull;
    float Dh = Dv[h];
    size_t tokBase = (size_t)b * SEQ;
    const float* xp = g_xs + tokBase * INTER + h * HEADDIM + p;
    const float4* Bg = (const float4*)(g_Bm + tokBase * STATE);   // 32 float4 per token
    const float4* Cg = (const float4*)(g_Cm + tokBase * STATE);
    const float* dAp = g_dA + tokBase * HEADS + h;
    const float* dtp = g_dt + tokBase * HEADS + h;
    float* yo = g_y + tokBase * INTER + h * HEADDIM + p;

    // loader mapping: 2 float4 per thread per matrix per chunk
    // f = tidx + j*256 (j<2): token tt = f>>5, quad q = f&31
    int lt0 = (tidx + 0) >> 5, lq0 = (tidx + 0) & 31;
    int lt1 = (tidx + 256) >> 5, lq1 = (tidx + 256) & 31;

    // prologue: load chunk 0 into buf 0
    {
        float4 b0 = Bg[(size_t)(0 + lt0) * 32 + lq0];
        float4 b1 = Bg[(size_t)(0 + lt1) * 32 + lq1];
        float4 c0 = Cg[(size_t)(0 + lt0) * 32 + lq0];
        float4 c1 = Cg[(size_t)(0 + lt1) * 32 + lq1];
        *(float4*)&sBC[0][lt0][lq0 * 4] = b0;
        *(float4*)&sBC[0][lt1][lq1 * 4] = b1;
        *(float4*)&sBC[0][lt0][STATE + lq0 * 4] = c0;
        *(float4*)&sBC[0][lt1][STATE + lq1 * 4] = c1;
    }
    __syncthreads();

    int nch = SEQ / TCH;
    for (int ck = 0; ck < nch; ck++) {
        int buf = ck & 1;
        // issue gmem loads for next chunk into registers (latency hidden by compute)
        float4 nb0, nb1, nc0, nc1;
        bool more = (ck + 1 < nch);
        if (more) {
            int t0 = (ck + 1) * TCH;
            nb0 = Bg[(size_t)(t0 + lt0) * 32 + lq0];
            nb1 = Bg[(size_t)(t0 + lt1) * 32 + lq1];
            nc0 = Cg[(size_t)(t0 + lt0) * 32 + lq0];
            nc1 = Cg[(size_t)(t0 + lt1) * 32 + lq1];
        }
        int tb = ck * TCH;
        #pragma unroll
        for (int ti = 0; ti < TCH; ti++) {
            int t = tb + ti;
            float dAv = dAp[(size_t)t * HEADS];
            float dtv = dtp[(size_t)t * HEADS];
            float xv = xp[(size_t)t * INTER];
            float xdt = xv * dtv;
            ull dA2 = pack2(dAv, dAv);
            ull xdt2 = pack2(xdt, xdt);
            const ulonglong2* B4 = (const ulonglong2*)&sBC[buf][ti][nc * 32];
            const ulonglong2* C4 = (const ulonglong2*)&sBC[buf][ti][STATE + nc * 32];
            ull y2 = pack2(0.f, 0.f);
            #pragma unroll
            for (int j = 0; j < 8; j++) {
                ulonglong2 bv = B4[j];
                ulonglong2 cv = C4[j];
                st2[2 * j]     = fma2(st2[2 * j],     dA2, mul2(xdt2, bv.x));
                y2             = fma2(st2[2 * j],     cv.x, y2);
                st2[2 * j + 1] = fma2(st2[2 * j + 1], dA2, mul2(xdt2, bv.y));
                y2             = fma2(st2[2 * j + 1], cv.y, y2);
            }
            float ylo, yhi;
            unpack2(y2, ylo, yhi);
            float ys = ylo + yhi;
            ys += __shfl_xor_sync(0xffffffffu, ys, 8);
            ys += __shfl_xor_sync(0xffffffffu, ys, 16);
            if (nc == 0) yo[(size_t)t * INTER] = ys + Dh * xv;
        }
        __syncthreads();
        if (more) {
            int nbuf = buf ^ 1;
            *(float4*)&sBC[nbuf][lt0][lq0 * 4] = nb0;
            *(float4*)&sBC[nbuf][lt1][lq1 * 4] = nb1;
            *(float4*)&sBC[nbuf][lt0][STATE + lq0 * 4] = nc0;
            *(float4*)&sBC[nbuf][lt1][STATE + lq1 * 4] = nc1;
            __syncthreads();
        }
    }
}

// ---------------- stage 6: gated rmsnorm ----------------
__global__ __launch_bounds__(256) void gatenorm_kernel(const float* __restrict__ gnw) {
    int row = blockIdx.x;
    const float* yrow = g_y + (size_t)row * INTER;
    const float* grow = g_proj + (size_t)row * PROJ_DIM;
    float vals[16];
    float ss = 0.f;
    #pragma unroll
    for (int i = 0; i < 16; i++) {
        int idx = threadIdx.x + i * 256;
        float gt = grow[idx];
        float v = yrow[idx] * fast_silu(gt);
        vals[i] = v;
        ss += v * v;
    }
    float tot = block_reduce_sum(ss);
    float scale = rsqrtf(tot * (1.f / INTER) + EPSV);
    float* orow = g_yn + (size_t)row * INTER;
    #pragma unroll
    for (int i = 0; i < 16; i++) {
        int idx = threadIdx.x + i * 256;
        orow[idx] = __uint_as_float(f2tf(vals[i] * scale * gnw[idx]));
    }
}

// ---------------- launch ----------------
extern "C" void kernel_launch(void* const* d_in, const int* in_sizes, int n_in,
                              void* d_out, int out_size) {
    const float* hidden  = (const float*)d_in[0];
    const float* norm_w  = (const float*)d_in[1];
    const float* in_proj = (const float*)d_in[2];
    const float* conv_w  = (const float*)d_in[3];
    const float* conv_b  = (const float*)d_in[4];
    const float* dt_bias = (const float*)d_in[5];
    const float* A_log   = (const float*)d_in[6];
    const float* Dvec    = (const float*)d_in[7];
    const float* gnw     = (const float*)d_in[8];
    const float* out_w   = (const float*)d_in[9];

    float *p_xn, *p_proj, *p_yn, *p_wa, *p_wb;
    cudaGetSymbolAddress((void**)&p_xn, g_xn);
    cudaGetSymbolAddress((void**)&p_proj, g_proj);
    cudaGetSymbolAddress((void**)&p_yn, g_yn);
    cudaGetSymbolAddress((void**)&p_wa, g_wa);
    cudaGetSymbolAddress((void**)&p_wb, g_wb);

    cudaFuncSetAttribute(gemm_tf32_nt, cudaFuncAttributeMaxDynamicSharedMemorySize, GEMM_SMEM);

    int n4a = (PROJ_DIM * HID) / 4;
    tf32_cvt_kernel<<<(n4a + 255) / 256, 256>>>(in_proj, p_wa, n4a);
    int n4b = (HID * INTER) / 4;
    tf32_cvt_kernel<<<(n4b + 255) / 256, 256>>>(out_w, p_wb, n4b);

    rmsnorm_in_kernel<<<NTOK, 256>>>(hidden, norm_w);

    gemm_tf32_nt<<<dim3((PROJ_DIM + 127) / 128, NTOK / 128), 128, GEMM_SMEM>>>(
        p_xn, p_wa, p_proj, nullptr, NTOK, PROJ_DIM, HID);

    conv_kernel<<<dim3(CONV_DIM / 128, NTOK / 64), 128>>>(conv_w, conv_b);

    dt_kernel<<<(NTOK * HEADS) / 256, 256>>>(dt_bias, A_log);

    scan_kernel<<<dim3(HEADS, 2), 256>>>(Dvec);

    gatenorm_kernel<<<NTOK, 256>>>(gnw);

    gemm_tf32_nt<<<dim3(HID / 128, NTOK / 128), 128, GEMM_SMEM>>>(
        p_yn, p_wb, (float*)d_out, hidden, NTOK, HID, INTER);
}

// round 9
// speedup vs baseline: 1.6436x; 1.0135x over previous
#include <cuda_runtime.h>
#include <cuda_bf16.h>
#include <cstdint>

#define HID 2048
#define STATE 128
#define HEADS 64
#define HEADDIM 64
#define INTER 4096
#define CONV_DIM 4352
#define PROJ_DIM 8512
#define NTOK 4096
#define SEQ 2048
#define EPSV 1e-5f

// ---------------- scratch ----------------
__device__ float g_xn[(size_t)NTOK * HID];
__device__ float g_proj[(size_t)NTOK * PROJ_DIM];
__device__ float g_xs[(size_t)NTOK * INTER];
__device__ float g_Bm[(size_t)NTOK * STATE];
__device__ float g_Cm[(size_t)NTOK * STATE];
__device__ float g_dt[(size_t)NTOK * HEADS];
__device__ float g_dA[(size_t)NTOK * HEADS];
__device__ float g_y[(size_t)NTOK * INTER];
__device__ float g_yn[(size_t)NTOK * INTER];
__device__ float g_wa[(size_t)PROJ_DIM * HID];
__device__ float g_wb[(size_t)HID * INTER];

// ---------------- helpers ----------------
__device__ __forceinline__ uint32_t f2tf(float f) {
    uint32_t r;
    asm("cvt.rna.tf32.f32 %0, %1;" : "=r"(r) : "f"(f));
    return r;
}

__device__ __forceinline__ uint32_t smem_u32(const void* p) {
    uint32_t a;
    asm("{ .reg .u64 t; cvta.to.shared.u64 t, %1; cvt.u32.u64 %0, t; }" : "=r"(a) : "l"(p));
    return a;
}

#define CP_ASYNC16(saddr, gptr) \
    asm volatile("cp.async.cg.shared.global [%0], [%1], 16;" :: "r"(saddr), "l"(gptr) : "memory")
#define CP_COMMIT() asm volatile("cp.async.commit_group;" ::: "memory")
#define CP_WAIT1()  asm volatile("cp.async.wait_group 1;" ::: "memory")

__device__ __forceinline__ float fast_silu(float a) {
    return __fdividef(a, 1.f + __expf(-a));
}

__device__ __forceinline__ float block_reduce_sum(float v) {
    __shared__ float sh[32];
    int lane = threadIdx.x & 31, w = threadIdx.x >> 5;
    #pragma unroll
    for (int o = 16; o; o >>= 1) v += __shfl_xor_sync(0xffffffffu, v, o);
    if (lane == 0) sh[w] = v;
    __syncthreads();
    int nw = blockDim.x >> 5;
    float t = (threadIdx.x < (unsigned)nw) ? sh[threadIdx.x] : 0.f;
    if (w == 0) {
        #pragma unroll
        for (int o = 16; o; o >>= 1) t += __shfl_xor_sync(0xffffffffu, t, o);
        if (lane == 0) sh[0] = t;
    }
    __syncthreads();
    return sh[0];
}

// f32x2 packed math
typedef unsigned long long ull;
__device__ __forceinline__ ull pack2(float lo, float hi) {
    ull r; asm("mov.b64 %0, {%1,%2};" : "=l"(r) : "f"(lo), "f"(hi)); return r;
}
__device__ __forceinline__ ull mul2(ull a, ull b) {
    ull r; asm("mul.rn.f32x2 %0, %1, %2;" : "=l"(r) : "l"(a), "l"(b)); return r;
}
__device__ __forceinline__ ull fma2(ull a, ull b, ull c) {
    ull r; asm("fma.rn.f32x2 %0, %1, %2, %3;" : "=l"(r) : "l"(a), "l"(b), "l"(c)); return r;
}
__device__ __forceinline__ ull add2(ull a, ull b) {
    ull r; asm("add.rn.f32x2 %0, %1, %2;" : "=l"(r) : "l"(a), "l"(b)); return r;
}
__device__ __forceinline__ void unpack2(ull v, float& lo, float& hi) {
    asm("mov.b64 {%0,%1}, %2;" : "=f"(lo), "=f"(hi) : "l"(v));
}

// ---------------- stage 0: convert weights to tf32 bits ----------------
__global__ __launch_bounds__(256) void tf32_cvt_kernel(
    const float* __restrict__ in, float* __restrict__ out, int n4) {
    int i = blockIdx.x * 256 + threadIdx.x;
    if (i >= n4) return;
    float4 v = ((const float4*)in)[i];
    uint4 u;
    u.x = f2tf(v.x); u.y = f2tf(v.y); u.z = f2tf(v.z); u.w = f2tf(v.w);
    ((uint4*)out)[i] = u;
}

// ---------------- stage 1: input rmsnorm (float4) ----------------
__global__ __launch_bounds__(256) void rmsnorm_in_kernel(
    const float* __restrict__ x, const float* __restrict__ w) {
    int row = blockIdx.x;
    const float4* xr = (const float4*)(x + (size_t)row * HID);
    const float4* w4 = (const float4*)w;
    float4 vals[2];
    float ss = 0.f;
    #pragma unroll
    for (int i = 0; i < 2; i++) {
        int idx = threadIdx.x + i * 256;
        float4 v = xr[idx];
        vals[i] = v;
        ss += v.x * v.x + v.y * v.y + v.z * v.z + v.w * v.w;
    }
    float tot = block_reduce_sum(ss);
    float scale = rsqrtf(tot * (1.f / HID) + EPSV);
    uint4* orow = (uint4*)(g_xn + (size_t)row * HID);
    #pragma unroll
    for (int i = 0; i < 2; i++) {
        int idx = threadIdx.x + i * 256;
        float4 ww = w4[idx];
        uint4 o;
        o.x = f2tf(vals[i].x * scale * ww.x);
        o.y = f2tf(vals[i].y * scale * ww.y);
        o.z = f2tf(vals[i].z * scale * ww.z);
        o.w = f2tf(vals[i].w * scale * ww.w);
        orow[idx] = o;
    }
}

// ---------------- TF32 NT GEMM: 128 thr, warptile 64x64, 3-stage, 1 barrier ----------------
#define BK 32
#define LDK 36
#define STAGE_FLOATS (128 * LDK)
#define GEMM_SMEM (3 * 2 * STAGE_FLOATS * 4)   // 110592 B

__global__ __launch_bounds__(128, 2) void gemm_tf32_nt(
    const float* __restrict__ A, const float* __restrict__ Bw,
    float* __restrict__ C, const float* __restrict__ Res,
    int M, int N, int K) {
    extern __shared__ float smf[];
    float* As = smf;                       // [3][128][LDK]
    float* Bs = smf + 3 * STAGE_FLOATS;
    uint32_t sA = smem_u32(As), sB = smem_u32(Bs);

    int tid = threadIdx.x;
    int mBase = blockIdx.y * 128, nBase = blockIdx.x * 128;
    int wid = tid >> 5, lane = tid & 31;
    int wm = wid >> 1, wn = wid & 1;     // 2 x 2 warps, warptile 64x64
    int g = lane >> 2, tg = lane & 3;
    int nk = K / BK;

    float acc[4][8][4];
    #pragma unroll
    for (int a = 0; a < 4; a++)
        #pragma unroll
        for (int b = 0; b < 8; b++)
            #pragma unroll
            for (int c = 0; c < 4; c++) acc[a][b][c] = 0.f;

    auto issue_tile = [&](int kt, int s) {
        size_t gk = (size_t)kt * BK;
        #pragma unroll
        for (int i = 0; i < 8; i++) {
            int idx = tid + i * 128;
            int row = idx >> 3, c4 = (idx & 7) * 4;
            uint32_t sa = sA + (uint32_t)(s * STAGE_FLOATS + row * LDK + c4) * 4u;
            CP_ASYNC16(sa, A + (size_t)(mBase + row) * K + gk + c4);
        }
        #pragma unroll
        for (int i = 0; i < 8; i++) {
            int idx = tid + i * 128;
            int row = idx >> 3, c4 = (idx & 7) * 4;
            if (nBase + row < N) {
                uint32_t sb2 = sB + (uint32_t)(s * STAGE_FLOATS + row * LDK + c4) * 4u;
                CP_ASYNC16(sb2, Bw + (size_t)(nBase + row) * K + gk + c4);
            }
        }
        CP_COMMIT();
    };

    issue_tile(0, 0);
    issue_tile(1, 1);

    // invariant at loop entry: pending groups = {kt, kt+1}
    int s_next = 2;
    for (int kt = 0; kt < nk; ++kt) {
        CP_WAIT1();          // own tile-kt parts done (1 group may remain in flight)
        __syncthreads();     // all warps' tile-kt data visible; all done with kt-1 MMAs

        if (kt + 2 < nk) {
            issue_tile(kt + 2, s_next);   // overwrites stage last read in iter kt-1: safe
        } else {
            CP_COMMIT();     // empty group keeps accounting
        }
        s_next++; if (s_next == 3) s_next = 0;

        int cur = kt % 3;
        const float* a_st = As + cur * STAGE_FLOATS;
        const float* b_st = Bs + cur * STAGE_FLOATS;
        #pragma unroll
        for (int kk = 0; kk < 4; ++kk) {
            uint32_t af[4][4], bf[8][2];
            int col = kk * 8 + tg;
            #pragma unroll
            for (int mt = 0; mt < 4; ++mt) {
                int row = wm * 64 + mt * 16 + g;
                af[mt][0] = __float_as_uint(a_st[row * LDK + col]);
                af[mt][1] = __float_as_uint(a_st[(row + 8) * LDK + col]);
                af[mt][2] = __float_as_uint(a_st[row * LDK + col + 4]);
                af[mt][3] = __float_as_uint(a_st[(row + 8) * LDK + col + 4]);
            }
            #pragma unroll
            for (int nt = 0; nt < 8; ++nt) {
                int nrow = wn * 64 + nt * 8 + g;
                bf[nt][0] = __float_as_uint(b_st[nrow * LDK + col]);
                bf[nt][1] = __float_as_uint(b_st[nrow * LDK + col + 4]);
            }
            #pragma unroll
            for (int mt = 0; mt < 4; ++mt)
                #pragma unroll
                for (int nt = 0; nt < 8; ++nt) {
                    asm volatile(
                        "mma.sync.aligned.m16n8k8.row.col.f32.tf32.tf32.f32 "
                        "{%0,%1,%2,%3},{%4,%5,%6,%7},{%8,%9},{%0,%1,%2,%3};\n"
                        : "+f"(acc[mt][nt][0]), "+f"(acc[mt][nt][1]),
                          "+f"(acc[mt][nt][2]), "+f"(acc[mt][nt][3])
                        : "r"(af[mt][0]), "r"(af[mt][1]), "r"(af[mt][2]), "r"(af[mt][3]),
                          "r"(bf[nt][0]), "r"(bf[nt][1]));
                }
        }
    }

    // epilogue
    #pragma unroll
    for (int mt = 0; mt < 4; ++mt) {
        int row0 = mBase + wm * 64 + mt * 16 + g;
        #pragma unroll
        for (int nt = 0; nt < 8; ++nt) {
            int col = nBase + wn * 64 + nt * 8 + tg * 2;
            if (col < N) {
                float v0 = acc[mt][nt][0];
                float v1 = acc[mt][nt][1];
                float v2 = acc[mt][nt][2];
                float v3 = acc[mt][nt][3];
                int row1 = row0 + 8;
                bool c1 = (col + 1 < N);
                if (Res) {
                    v0 += Res[(size_t)row0 * N + col];
                    if (c1) v1 += Res[(size_t)row0 * N + col + 1];
                    v2 += Res[(size_t)row1 * N + col];
                    if (c1) v3 += Res[(size_t)row1 * N + col + 1];
                }
                C[(size_t)row0 * N + col] = v0;
                if (c1) C[(size_t)row0 * N + col + 1] = v1;
                C[(size_t)row1 * N + col] = v2;
                if (c1) C[(size_t)row1 * N + col + 1] = v3;
            }
        }
    }
}

// ---------------- stage 3: conv (K=4) + SiLU + split, 4 channels/thread ----------------
__global__ __launch_bounds__(64) void conv_kernel(
    const float* __restrict__ conv_w, const float* __restrict__ conv_b) {
    int c = (blockIdx.x * 64 + threadIdx.x) * 4;   // channel quad base
    int t0 = blockIdx.y * 64;
    float4 wt[4];   // wt[k].{x,y,z,w} = tap k of channels c..c+3
    {
        float4 a = *(const float4*)&conv_w[(c + 0) * 4];
        float4 b = *(const float4*)&conv_w[(c + 1) * 4];
        float4 d = *(const float4*)&conv_w[(c + 2) * 4];
        float4 e = *(const float4*)&conv_w[(c + 3) * 4];
        wt[0] = make_float4(a.x, b.x, d.x, e.x);
        wt[1] = make_float4(a.y, b.y, d.y, e.y);
        wt[2] = make_float4(a.z, b.z, d.z, e.z);
        wt[3] = make_float4(a.w, b.w, d.w, e.w);
    }
    float4 bias = *(const float4*)&conv_b[c];
    const float* col = g_proj + INTER + c;
    float4 h0, h1, h2;
    if ((t0 & (SEQ - 1)) == 0) {
        h0 = h1 = h2 = make_float4(0.f, 0.f, 0.f, 0.f);
    } else {
        h0 = *(const float4*)&col[(size_t)(t0 - 3) * PROJ_DIM];
        h1 = *(const float4*)&col[(size_t)(t0 - 2) * PROJ_DIM];
        h2 = *(const float4*)&col[(size_t)(t0 - 1) * PROJ_DIM];
    }
    for (int i = 0; i < 64; i++) {
        int t = t0 + i;
        float4 xc = *(const float4*)&col[(size_t)t * PROJ_DIM];
        float4 v;
        v.x = fast_silu(bias.x + wt[0].x * h0.x + wt[1].x * h1.x + wt[2].x * h2.x + wt[3].x * xc.x);
        v.y = fast_silu(bias.y + wt[0].y * h0.y + wt[1].y * h1.y + wt[2].y * h2.y + wt[3].y * xc.y);
        v.z = fast_silu(bias.z + wt[0].z * h0.z + wt[1].z * h1.z + wt[2].z * h2.z + wt[3].z * xc.z);
        v.w = fast_silu(bias.w + wt[0].w * h0.w + wt[1].w * h1.w + wt[2].w * h2.w + wt[3].w * xc.w);
        if (c < INTER)
            *(float4*)&g_xs[(size_t)t * INTER + c] = v;
        else if (c < INTER + STATE)
            *(float4*)&g_Bm[(size_t)t * STATE + (c - INTER)] = v;
        else
            *(float4*)&g_Cm[(size_t)t * STATE + (c - INTER - STATE)] = v;
        h0 = h1; h1 = h2; h2 = xc;
    }
}

// ---------------- stage 4: dt / dA ----------------
__global__ __launch_bounds__(256) void dt_kernel(
    const float* __restrict__ dt_bias, const float* __restrict__ A_log) {
    int i = blockIdx.x * 256 + threadIdx.x;
    if (i >= NTOK * HEADS) return;
    int h = i & (HEADS - 1);
    int tok = i >> 6;
    float raw = g_proj[(size_t)tok * PROJ_DIM + INTER + CONV_DIM + h];
    float s = raw + dt_bias[h];
    float dtv = (s > 20.f) ? s : log1pf(expf(s));
    float Aval = -expf(A_log[h]);
    g_dt[i] = dtv;
    g_dA[i] = expf(dtv * Aval);
}

// ---------------- stage 5: selective scan, smem-staged, split y-chains ----------------
#define TCH 16
__global__ __launch_bounds__(256) void scan_kernel(const float* __restrict__ Dv) {
    __shared__ float sBC[2][TCH][2 * STATE];
    int h = blockIdx.x, b = blockIdx.y;
    int tidx = threadIdx.x;
    int lane = tidx & 31, w = tidx >> 5;
    int pi = lane & 7, nc = lane >> 3;
    int p = w * 8 + pi;
    ull st2[16];
    #pragma unroll
    for (int i = 0; i < 16; i++) st2[i] = 0ull;
    float Dh = Dv[h];
    size_t tokBase = (size_t)b * SEQ;
    const float* xp = g_xs + tokBase * INTER + h * HEADDIM + p;
    const float4* Bg = (const float4*)(g_Bm + tokBase * STATE);
    const float4* Cg = (const float4*)(g_Cm + tokBase * STATE);
    const float* dAp = g_dA + tokBase * HEADS + h;
    const float* dtp = g_dt + tokBase * HEADS + h;
    float* yo = g_y + tokBase * INTER + h * HEADDIM + p;

    int lt0 = (tidx + 0) >> 5, lq0 = (tidx + 0) & 31;
    int lt1 = (tidx + 256) >> 5, lq1 = (tidx + 256) & 31;

    {
        float4 b0 = Bg[(size_t)lt0 * 32 + lq0];
        float4 b1 = Bg[(size_t)lt1 * 32 + lq1];
        float4 c0 = Cg[(size_t)lt0 * 32 + lq0];
        float4 c1 = Cg[(size_t)lt1 * 32 + lq1];
        *(float4*)&sBC[0][lt0][lq0 * 4] = b0;
        *(float4*)&sBC[0][lt1][lq1 * 4] = b1;
        *(float4*)&sBC[0][lt0][STATE + lq0 * 4] = c0;
        *(float4*)&sBC[0][lt1][STATE + lq1 * 4] = c1;
    }
    __syncthreads();

    int nch = SEQ / TCH;
    for (int ck = 0; ck < nch; ck++) {
        int buf = ck & 1;
        float4 nb0, nb1, nc0, nc1;
        bool more = (ck + 1 < nch);
        if (more) {
            int t0 = (ck + 1) * TCH;
            nb0 = Bg[(size_t)(t0 + lt0) * 32 + lq0];
            nb1 = Bg[(size_t)(t0 + lt1) * 32 + lq1];
            nc0 = Cg[(size_t)(t0 + lt0) * 32 + lq0];
            nc1 = Cg[(size_t)(t0 + lt1) * 32 + lq1];
        }
        int tb = ck * TCH;
        #pragma unroll
        for (int ti = 0; ti < TCH; ti++) {
            int t = tb + ti;
            float dAv = dAp[(size_t)t * HEADS];
            float dtv = dtp[(size_t)t * HEADS];
            float xv = xp[(size_t)t * INTER];
            float xdt = xv * dtv;
            ull dA2 = pack2(dAv, dAv);
            ull xdt2 = pack2(xdt, xdt);
            const ulonglong2* B4 = (const ulonglong2*)&sBC[buf][ti][nc * 32];
            const ulonglong2* C4 = (const ulonglong2*)&sBC[buf][ti][STATE + nc * 32];
            ull ya = pack2(0.f, 0.f), yb = ya, yc = ya, yd = ya;
            #pragma unroll
            for (int j = 0; j < 4; j++) {
                ulonglong2 bv0 = B4[2 * j];
                ulonglong2 cv0 = C4[2 * j];
                ulonglong2 bv1 = B4[2 * j + 1];
                ulonglong2 cv1 = C4[2 * j + 1];
                st2[4 * j + 0] = fma2(st2[4 * j + 0], dA2, mul2(xdt2, bv0.x));
                ya             = fma2(st2[4 * j + 0], cv0.x, ya);
                st2[4 * j + 1] = fma2(st2[4 * j + 1], dA2, mul2(xdt2, bv0.y));
                yb             = fma2(st2[4 * j + 1], cv0.y, yb);
                st2[4 * j + 2] = fma2(st2[4 * j + 2], dA2, mul2(xdt2, bv1.x));
                yc             = fma2(st2[4 * j + 2], cv1.x, yc);
                st2[4 * j + 3] = fma2(st2[4 * j + 3], dA2, mul2(xdt2, bv1.y));
                yd             = fma2(st2[4 * j + 3], cv1.y, yd);
            }
            ull ysum = add2(add2(ya, yb), add2(yc, yd));
            float ylo, yhi;
            unpack2(ysum, ylo, yhi);
            float ys = ylo + yhi;
            ys += __shfl_xor_sync(0xffffffffu, ys, 8);
            ys += __shfl_xor_sync(0xffffffffu, ys, 16);
            if (nc == 0) yo[(size_t)t * INTER] = ys + Dh * xv;
        }
        __syncthreads();
        if (more) {
            int nbuf = buf ^ 1;
            *(float4*)&sBC[nbuf][lt0][lq0 * 4] = nb0;
            *(float4*)&sBC[nbuf][lt1][lq1 * 4] = nb1;
            *(float4*)&sBC[nbuf][lt0][STATE + lq0 * 4] = nc0;
            *(float4*)&sBC[nbuf][lt1][STATE + lq1 * 4] = nc1;
            __syncthreads();
        }
    }
}

// ---------------- stage 6: gated rmsnorm (float4) ----------------
__global__ __launch_bounds__(256) void gatenorm_kernel(const float* __restrict__ gnw) {
    int row = blockIdx.x;
    const float4* yrow = (const float4*)(g_y + (size_t)row * INTER);
    const float4* grow = (const float4*)(g_proj + (size_t)row * PROJ_DIM);
    const float4* gw4 = (const float4*)gnw;
    float4 vals[4];
    float ss = 0.f;
    #pragma unroll
    for (int i = 0; i < 4; i++) {
        int idx = threadIdx.x + i * 256;
        float4 gt = grow[idx];
        float4 yv = yrow[idx];
        float4 v;
        v.x = yv.x * fast_silu(gt.x);
        v.y = yv.y * fast_silu(gt.y);
        v.z = yv.z * fast_silu(gt.z);
        v.w = yv.w * fast_silu(gt.w);
        vals[i] = v;
        ss += v.x * v.x + v.y * v.y + v.z * v.z + v.w * v.w;
    }
    float tot = block_reduce_sum(ss);
    float scale = rsqrtf(tot * (1.f / INTER) + EPSV);
    uint4* orow = (uint4*)(g_yn + (size_t)row * INTER);
    #pragma unroll
    for (int i = 0; i < 4; i++) {
        int idx = threadIdx.x + i * 256;
        float4 ww = gw4[idx];
        uint4 o;
        o.x = f2tf(vals[i].x * scale * ww.x);
        o.y = f2tf(vals[i].y * scale * ww.y);
        o.z = f2tf(vals[i].z * scale * ww.z);
        o.w = f2tf(vals[i].w * scale * ww.w);
        orow[idx] = o;
    }
}

// ---------------- launch ----------------
extern "C" void kernel_launch(void* const* d_in, const int* in_sizes, int n_in,
                              void* d_out, int out_size) {
    const float* hidden  = (const float*)d_in[0];
    const float* norm_w  = (const float*)d_in[1];
    const float* in_proj = (const float*)d_in[2];
    const float* conv_w  = (const float*)d_in[3];
    const float* conv_b  = (const float*)d_in[4];
    const float* dt_bias = (const float*)d_in[5];
    const float* A_log   = (const float*)d_in[6];
    const float* Dvec    = (const float*)d_in[7];
    const float* gnw     = (const float*)d_in[8];
    const float* out_w   = (const float*)d_in[9];

    float *p_xn, *p_proj, *p_yn, *p_wa, *p_wb;
    cudaGetSymbolAddress((void**)&p_xn, g_xn);
    cudaGetSymbolAddress((void**)&p_proj, g_proj);
    cudaGetSymbolAddress((void**)&p_yn, g_yn);
    cudaGetSymbolAddress((void**)&p_wa, g_wa);
    cudaGetSymbolAddress((void**)&p_wb, g_wb);

    cudaFuncSetAttribute(gemm_tf32_nt, cudaFuncAttributeMaxDynamicSharedMemorySize, GEMM_SMEM);

    int n4a = (PROJ_DIM * HID) / 4;
    tf32_cvt_kernel<<<(n4a + 255) / 256, 256>>>(in_proj, p_wa, n4a);
    int n4b = (HID * INTER) / 4;
    tf32_cvt_kernel<<<(n4b + 255) / 256, 256>>>(out_w, p_wb, n4b);

    rmsnorm_in_kernel<<<NTOK, 256>>>(hidden, norm_w);

    gemm_tf32_nt<<<dim3((PROJ_DIM + 127) / 128, NTOK / 128), 128, GEMM_SMEM>>>(
        p_xn, p_wa, p_proj, nullptr, NTOK, PROJ_DIM, HID);

    conv_kernel<<<dim3(CONV_DIM / 4 / 64, NTOK / 64), 64>>>(conv_w, conv_b);

    dt_kernel<<<(NTOK * HEADS) / 256, 256>>>(dt_bias, A_log);

    scan_kernel<<<dim3(HEADS, 2), 256>>>(Dvec);

    gatenorm_kernel<<<NTOK, 256>>>(gnw);

    gemm_tf32_nt<<<dim3(HID / 128, NTOK / 128), 128, GEMM_SMEM>>>(
        p_yn, p_wb, (float*)d_out, hidden, NTOK, HID, INTER);
}